// round 12
// baseline (speedup 1.0000x reference)
#include <cuda_runtime.h>
#include <cuda_bf16.h>
#include <cstdint>

#define Bsz 16
#define Ntok 4096
#define Cch 384
#define HRES 64
#define NH 12
#define DH 32
#define TWOC 768

// Scratch (device globals: allocation-free rule)
__device__ __nv_bfloat16 g_xbf[Bsz * Ntok * Cch];   // bf16 copy of x
__device__ __nv_bfloat16 g_wbf[TWOC * Cch];         // bf16 copy of qk_w
__device__ __nv_bfloat16 g_qrb[Bsz * Ntok * Cch];   // roped q (bf16)
__device__ __nv_bfloat16 g_krb[Bsz * Ntok * Cch];   // roped k (bf16)
__device__ float  g_ksum[Bsz * Cch];                // sum_n k (unroped, fp32)
__device__ float  g_kv  [Bsz * NH * DH * DH];
__device__ float2 g_rope[Ntok * (Cch / 2)];

// ---------------------------------------------------------------------------
__device__ __forceinline__ uint32_t packbf(float a, float b) {
    __nv_bfloat162 h = __float22bfloat162_rn(make_float2(a, b));
    return *reinterpret_cast<uint32_t*>(&h);
}

__device__ __forceinline__ void ldm_x4(uint32_t* d, uint32_t addr) {
    asm volatile("ldmatrix.sync.aligned.m8n8.x4.shared.b16 {%0,%1,%2,%3}, [%4];"
                 : "=r"(d[0]), "=r"(d[1]), "=r"(d[2]), "=r"(d[3]) : "r"(addr));
}

__device__ __forceinline__ void mma16(float4& d, const uint32_t* a,
                                      uint32_t b0, uint32_t b1) {
    asm volatile(
        "mma.sync.aligned.m16n8k16.row.col.f32.bf16.bf16.f32 "
        "{%0,%1,%2,%3},{%4,%5,%6,%7},{%8,%9},{%0,%1,%2,%3};\n"
        : "+f"(d.x), "+f"(d.y), "+f"(d.z), "+f"(d.w)
        : "r"(a[0]), "r"(a[1]), "r"(a[2]), "r"(a[3]), "r"(b0), "r"(b1));
}

__device__ __forceinline__ void cp16(uint32_t smem, const void* g) {
    asm volatile("cp.async.cg.shared.global [%0], [%1], 16;" :: "r"(smem), "l"(g));
}

// ---------------------------------------------------------------------------
// Fused setup: rope table + zero scratch + bf16 conversion, one launch.
// ---------------------------------------------------------------------------
#define SB_ROPE 3072
#define SB_ZERO (SB_ROPE + 768)
#define SB_X    (SB_ZERO + 12288)
#define SB_W    (SB_X + 144)

__global__ __launch_bounds__(256) void setup_kernel(
    const float* __restrict__ x, const float* __restrict__ w)
{
    int blk = blockIdx.x;
    if (blk < SB_ROPE) {
        int i = blk * 256 + threadIdx.x;      // < 786432
        int n = i / 192, p = i % 192;
        int hh = n >> 6, ww = n & 63;
        int j = (p < 96) ? p : (p - 96);
        float theta = __expf(-((float)j * (1.0f / 96.0f)) * 9.210340371976184f);
        float pos = (p < 96) ? (float)hh : (float)ww;
        float s, c;
        sincosf(pos * theta, &s, &c);
        g_rope[(size_t)n * 192 + p] = make_float2(c, s);
    } else if (blk < SB_ZERO) {
        int i = (blk - SB_ROPE) * 256 + threadIdx.x;   // < 196608
        if (i < Bsz * Cch) g_ksum[i] = 0.f;
        g_kv[i] = 0.f;
    } else if (blk < SB_X) {
        size_t o = ((size_t)(blk - SB_ZERO) * 256 + threadIdx.x) * 8;
        float4 a = *(const float4*)(x + o);
        float4 b = *(const float4*)(x + o + 4);
        uint4 u = make_uint4(packbf(a.x, a.y), packbf(a.z, a.w),
                             packbf(b.x, b.y), packbf(b.z, b.w));
        *(uint4*)&g_xbf[o] = u;
    } else {
        size_t o = ((size_t)(blk - SB_X) * 256 + threadIdx.x) * 8;
        if (o < (size_t)TWOC * Cch) {
            float4 a = *(const float4*)(w + o);
            float4 b = *(const float4*)(w + o + 4);
            uint4 u = make_uint4(packbf(a.x, a.y), packbf(a.z, a.w),
                                 packbf(b.x, b.y), packbf(b.z, b.w));
            *(uint4*)&g_wbf[o] = u;
        }
    }
}

// ---------------------------------------------------------------------------
// GEMM qk = x @ W^T + b via bf16 MMA, BK=64 K-tiles, 2-stage double buffer.
// BM=128 BN=128, 256 threads (8 warps: 2 in M x 4 in N), warp 64x32.
// One barrier per 64-K tile (6 total vs 12 at BK=32).
// ---------------------------------------------------------------------------
#define BM 128
#define BN 128
#define BK 64
#define NKT (Cch / BK)          // 6
#define AROW 144                 // bytes per smem row (64 bf16 data + 16 pad)
#define ATILE (BM * AROW)        // 18432
#define WTILE (BN * AROW)        // 18432
#define GEMM_SMEM (2 * (ATILE + WTILE))   // 73728

__global__ __launch_bounds__(256, 2) void gemm_rope_tc(const float* __restrict__ bias)
{
    extern __shared__ __align__(16) uint8_t gsm[];
    uint8_t* smA = gsm;
    uint8_t* smW = gsm + 2 * ATILE;

    int tid  = threadIdx.x;
    int warp = tid >> 5, lane = tid & 31;
    int wm = warp >> 2, wn = warp & 3;
    int g  = lane >> 2, l4 = lane & 3;
    int r8 = lane & 7,  qq = lane >> 3;

    int jBase = blockIdx.x * BN;
    int mBase = blockIdx.y * BM;

    const __nv_bfloat16* xblk = g_xbf + (size_t)mBase * Cch;
    const __nv_bfloat16* wblk = g_wbf + (size_t)jBase * Cch;

    // loader coords: 1024 16B-chunks per tile per array, 4 per thread
    int lr[4], lch[4];
#pragma unroll
    for (int i = 0; i < 4; i++) {
        int idx = tid + i * 256;
        lr[i]  = idx >> 3;          // row 0..127
        lch[i] = idx & 7;           // chunk 0..7 (16B each)
    }

    uint32_t aBase = (uint32_t)__cvta_generic_to_shared(smA);
    uint32_t wBase = (uint32_t)__cvta_generic_to_shared(smW);
    uint32_t aOff = (uint32_t)(((qq & 1) * 8 + r8) * AROW + (qq >> 1) * 16);
    uint32_t bOff = (uint32_t)(((qq >> 1) * 8 + r8) * AROW + (qq & 1) * 16);

    auto loadTile = [&](int t, int buf) {
        int k0 = t * BK;
#pragma unroll
        for (int i = 0; i < 4; i++) {
            uint32_t so = (uint32_t)(buf * ATILE + lr[i] * AROW + lch[i] * 16);
            size_t go = (size_t)lr[i] * Cch + k0 + lch[i] * 8;
            cp16(aBase + so, xblk + go);
            cp16(wBase + so, wblk + go);
        }
        asm volatile("cp.async.commit_group;");
    };

    float4 c[4][4];
#pragma unroll
    for (int i = 0; i < 4; i++)
#pragma unroll
        for (int f = 0; f < 4; f++) c[i][f] = make_float4(0.f, 0.f, 0.f, 0.f);

    loadTile(0, 0);

    for (int t = 0; t < NKT; t++) {
        asm volatile("cp.async.wait_group 0;");   // tile t complete (only outstanding)
        __syncthreads();                           // all warps past compute(t-1)
        if (t + 1 < NKT) loadTile(t + 1, (t + 1) & 1);

        int buf = t & 1;
        uint32_t aT = aBase + (uint32_t)(buf * ATILE);
        uint32_t wT = wBase + (uint32_t)(buf * WTILE);
#pragma unroll
        for (int kk = 0; kk < BK; kk += 16) {
            uint32_t a[4][4], b[2][4];
#pragma unroll
            for (int mi = 0; mi < 4; mi++)
                ldm_x4(a[mi], aT + (uint32_t)((wm * 64 + mi * 16) * AROW + kk * 2) + aOff);
#pragma unroll
            for (int bg = 0; bg < 2; bg++)
                ldm_x4(b[bg], wT + (uint32_t)((wn * 32 + bg * 16) * AROW + kk * 2) + bOff);
#pragma unroll
            for (int mi = 0; mi < 4; mi++)
#pragma unroll
                for (int bg = 0; bg < 2; bg++) {
                    mma16(c[mi][bg * 2],     a[mi], b[bg][0], b[bg][1]);
                    mma16(c[mi][bg * 2 + 1], a[mi], b[bg][2], b[bg][3]);
                }
        }
    }

    // ---- fused epilogue: bias, elu+1, RoPE, k-sum; bf16 outputs ----
    bool isK = (jBase >= Cch);
    int bb = mBase >> 12;
    float ksum_loc[4][2];
#pragma unroll
    for (int f = 0; f < 4; f++) { ksum_loc[f][0] = 0.f; ksum_loc[f][1] = 0.f; }

#pragma unroll
    for (int mi = 0; mi < 4; mi++) {
        int mrow0 = mBase + wm * 64 + mi * 16 + g;
#pragma unroll
        for (int f = 0; f < 4; f++) {
            int j0 = jBase + wn * 32 + f * 8 + 2 * l4;
            int jm = isK ? (j0 - Cch) : j0;
            float b0 = bias[j0], b1 = bias[j0 + 1];
#pragma unroll
            for (int rr = 0; rr < 2; rr++) {
                int m = mrow0 + rr * 8;
                float re = (rr == 0 ? c[mi][f].x : c[mi][f].z) + b0;
                float im = (rr == 0 ? c[mi][f].y : c[mi][f].w) + b1;
                re = (re > 0.f) ? (re + 1.f) : __expf(re);
                im = (im > 0.f) ? (im + 1.f) : __expf(im);
                int n = m & (Ntok - 1);
                float2 cs = g_rope[(size_t)n * 192 + (jm >> 1)];
                float rre = cs.x * re - cs.y * im;
                float rim = cs.y * re + cs.x * im;
                size_t off = (size_t)m * Cch + jm;
                uint32_t pk = packbf(rre, rim);
                if (!isK) {
                    *(uint32_t*)&g_qrb[off] = pk;
                } else {
                    *(uint32_t*)&g_krb[off] = pk;
                    ksum_loc[f][0] += re;
                    ksum_loc[f][1] += im;
                }
            }
        }
    }

    if (isK) {
#pragma unroll
        for (int f = 0; f < 4; f++) {
#pragma unroll
            for (int e = 0; e < 2; e++) {
                float v = ksum_loc[f][e];
                v += __shfl_xor_sync(0xffffffffu, v, 4);
                v += __shfl_xor_sync(0xffffffffu, v, 8);
                v += __shfl_xor_sync(0xffffffffu, v, 16);
                if (g == 0) {
                    int jm = (jBase - Cch) + wn * 32 + f * 8 + 2 * l4 + e;
                    atomicAdd(&g_ksum[bb * Cch + jm], v);
                }
            }
        }
    }
}

// ---------------------------------------------------------------------------
// kv[b][h] += (1/N) sum_n outer(k_rope, v);  bf16 inputs, fp32 accumulate.
// ---------------------------------------------------------------------------
#define KVCH 32
#define KVSPLIT 32
#define KVROW 256
#define KVTILE (KVCH * KVROW)

__global__ __launch_bounds__(256) void kv_kernel()
{
    int b = blockIdx.x, hq = blockIdx.y, s = blockIdx.z;
    int tid = threadIdx.x;
    __shared__ __align__(16) uint8_t ksm[2 * KVTILE];
    __shared__ __align__(16) uint8_t vsm[2 * KVTILE];

    int sub = tid >> 6;
    int st  = tid & 63;
    int d0  = (st >> 3) * 4;
    int e0  = (st & 7) * 4;

    float a[4][4];
#pragma unroll
    for (int r = 0; r < 4; r++)
#pragma unroll
        for (int cc = 0; cc < 4; cc++) a[r][cc] = 0.f;

    const int CHUNK = Ntok / KVSPLIT;
    const int NSTG  = CHUNK / KVCH;
    int nBase = s * CHUNK;
    const __nv_bfloat16* kr = g_krb + ((size_t)b * Ntok + nBase) * Cch + hq * 128;
    const __nv_bfloat16* vv = g_xbf + ((size_t)b * Ntok + nBase) * Cch + hq * 128;

    int ln[2], lc[2];
#pragma unroll
    for (int i = 0; i < 2; i++) { int idx = tid + i * 256; ln[i] = idx >> 4; lc[i] = (idx & 15) * 8; }
    uint32_t ksB = (uint32_t)__cvta_generic_to_shared(ksm);
    uint32_t vsB = (uint32_t)__cvta_generic_to_shared(vsm);

    auto load_stage = [&](int stg, int buf) {
#pragma unroll
        for (int i = 0; i < 2; i++) {
            uint32_t so = (uint32_t)(buf * KVTILE + ln[i] * KVROW + lc[i] * 2);
            size_t go = (size_t)(stg * KVCH + ln[i]) * Cch + lc[i];
            cp16(ksB + so, kr + go);
            cp16(vsB + so, vv + go);
        }
        asm volatile("cp.async.commit_group;");
    };

    load_stage(0, 0);
    for (int stg = 0; stg < NSTG; stg++) {
        if (stg + 1 < NSTG) {
            load_stage(stg + 1, (stg + 1) & 1);
            asm volatile("cp.async.wait_group 1;");
        } else {
            asm volatile("cp.async.wait_group 0;");
        }
        __syncthreads();
        int buf = stg & 1;
        const uint8_t* kb = ksm + buf * KVTILE + (sub * 32 + d0) * 2;
        const uint8_t* vb = vsm + buf * KVTILE + (sub * 32 + e0) * 2;
#pragma unroll
        for (int n = 0; n < KVCH; n++) {
            const __nv_bfloat162* kp = (const __nv_bfloat162*)(kb + n * KVROW);
            const __nv_bfloat162* vp = (const __nv_bfloat162*)(vb + n * KVROW);
            float2 k01 = __bfloat1622float2(kp[0]);
            float2 k23 = __bfloat1622float2(kp[1]);
            float2 v01 = __bfloat1622float2(vp[0]);
            float2 v23 = __bfloat1622float2(vp[1]);
            float kk[4] = {k01.x, k01.y, k23.x, k23.y};
            float vr[4] = {v01.x, v01.y, v23.x, v23.y};
#pragma unroll
            for (int r = 0; r < 4; r++)
#pragma unroll
                for (int cc = 0; cc < 4; cc++) a[r][cc] += kk[r] * vr[cc];
        }
        __syncthreads();
    }

    const float inv = 1.0f / (float)Ntok;
    float* dst = g_kv + (size_t)(b * NH + hq * 4 + sub) * DH * DH;
#pragma unroll
    for (int r = 0; r < 4; r++)
#pragma unroll
        for (int cc = 0; cc < 4; cc++)
            atomicAdd(&dst[(d0 + r) * DH + e0 + cc], a[r][cc] * inv);
}

// ---------------------------------------------------------------------------
// Finalize: tensor-core attention epilogue + chunked depthwise conv (fp32 x).
// SMEM UNION (57KB) + __launch_bounds__(384,3): 3 blocks/SM.
// ---------------------------------------------------------------------------
#define FQ_BYTES 784
#define FQ_SIZE  (32 * FQ_BYTES)            // 25088
#define FB_OFF   FQ_SIZE
#define FB_SIZE  (NH * DH * 80)             // 30720
#define FO_STRIDE 388
#define FO_SIZE  (32 * FO_STRIDE * 4)       // 49664  (< FQ_SIZE + FB_SIZE)
#define FZ_OFF   (FQ_SIZE + FB_SIZE)        // 55808
#define FIN_SMEM (FZ_OFF + NH * 32 * 4)     // 57344

__global__ __launch_bounds__(384, 3) void finalize_kernel(
    const float* __restrict__ x, const float* __restrict__ lepe_w,
    const float* __restrict__ lepe_b, float* __restrict__ out)
{
    extern __shared__ __align__(16) uint8_t fsm[];
    __nv_bfloat16* Q = (__nv_bfloat16*)fsm;
    uint8_t* Bkv = fsm + FB_OFF;
    float* O  = (float*)fsm;                 // union: valid after MMA+sync
    float* zs = (float*)(fsm + FZ_OFF);

    int hh = blockIdx.x, half = blockIdx.y, b = blockIdx.z;
    int t = threadIdx.x;
    int h = t >> 5, lane = t & 31;
    bool even = ((lane & 1) == 0);
    int n0 = hh * HRES + half * 32;

    uint32_t qB = (uint32_t)__cvta_generic_to_shared(Q);

    {
        const __nv_bfloat16* qsrc = g_qrb + ((size_t)b * Ntok + n0) * Cch;
#pragma unroll
        for (int i = 0; i < 4; i++) {
            int idx = i * 384 + t;
            int row = idx / 48, col = idx % 48;
            cp16(qB + (uint32_t)(row * FQ_BYTES + col * 16),
                 qsrc + (size_t)row * Cch + col * 8);
        }
        asm volatile("cp.async.commit_group;");
    }

    float km  = g_ksum[b * Cch + t] * (1.0f / (float)Ntok);
    float kmp = __shfl_xor_sync(0xffffffffu, km, 1);

    {
        const float* kvh = g_kv + (size_t)(b * NH + h) * DH * DH;
        __nv_bfloat16* Bh = (__nv_bfloat16*)(Bkv + h * (DH * 80));
#pragma unroll
        for (int d = 0; d < DH; d++) {
            float v = kvh[d * DH + lane];
            Bh[lane * 40 + d] = __float2bfloat16(v);
        }
    }

    asm volatile("cp.async.wait_group 0;");
    __syncthreads();

#pragma unroll 4
    for (int w = 0; w < 32; w++) {
        float2 cs = g_rope[(size_t)(n0 + w) * 192 + (h * 16 + (lane >> 1))];
        float qv = __bfloat162float(Q[w * 392 + h * 32 + lane]);
        float rkm = even ? (cs.x * km - cs.y * kmp) : (cs.y * kmp + cs.x * km);
        float prod = qv * rkm;
#pragma unroll
        for (int o = 16; o > 0; o >>= 1)
            prod += __shfl_xor_sync(0xffffffffu, prod, o);
        if (lane == 0) zs[h * 32 + w] = 1.0f / (prod + 1e-6f);
    }
    __syncwarp();

    float4 c[2][4];
#pragma unroll
    for (int i = 0; i < 2; i++)
#pragma unroll
        for (int f = 0; f < 4; f++) c[i][f] = make_float4(0.f, 0.f, 0.f, 0.f);
    {
        int qq = lane >> 3, r8 = lane & 7;
        uint32_t aOff = (uint32_t)(((qq & 1) * 8 + r8) * FQ_BYTES + (qq >> 1) * 16);
        uint32_t bOff = (uint32_t)(((qq >> 1) * 8 + r8) * 80 + (qq & 1) * 16);
        uint32_t bB = (uint32_t)__cvta_generic_to_shared(Bkv) + (uint32_t)(h * DH * 80);
#pragma unroll
        for (int kk = 0; kk < 32; kk += 16) {
            uint32_t a[2][4], bb[2][4];
#pragma unroll
            for (int tf = 0; tf < 2; tf++)
                ldm_x4(a[tf], qB + (uint32_t)(tf * 16 * FQ_BYTES + (h * 32 + kk) * 2) + aOff);
#pragma unroll
            for (int bg = 0; bg < 2; bg++)
                ldm_x4(bb[bg], bB + (uint32_t)(bg * 16 * 80 + kk * 2) + bOff);
#pragma unroll
            for (int tf = 0; tf < 2; tf++)
#pragma unroll
                for (int bg = 0; bg < 2; bg++) {
                    mma16(c[tf][bg * 2],     a[tf], bb[bg][0], bb[bg][1]);
                    mma16(c[tf][bg * 2 + 1], a[tf], bb[bg][2], bb[bg][3]);
                }
        }
    }

    // Phase boundary: Q/Bkv dead, O takes over the same smem.
    __syncthreads();

    {
        int g = lane >> 2, l4 = lane & 3;
#pragma unroll
        for (int tf = 0; tf < 2; tf++) {
            float zlo = zs[h * 32 + tf * 16 + g];
            float zhi = zs[h * 32 + tf * 16 + g + 8];
#pragma unroll
            for (int f = 0; f < 4; f++) {
                int e = h * 32 + f * 8 + 2 * l4;
                float* lo = &O[(tf * 16 + g) * FO_STRIDE + e];
                float* hi = &O[(tf * 16 + g + 8) * FO_STRIDE + e];
                lo[0] = c[tf][f].x * zlo;  lo[1] = c[tf][f].y * zlo;
                hi[0] = c[tf][f].z * zhi;  hi[1] = c[tf][f].w * zhi;
            }
        }
    }
    __syncthreads();

    // Phase 4: chunked depthwise 3x3 conv (fp32 x) + add O
    float wl[9];
#pragma unroll
    for (int i = 0; i < 9; i++) wl[i] = lepe_w[t * 9 + i];
    float lb = lepe_b[t];

    const size_t rowStride = (size_t)HRES * Cch;
    const float* xb = x + (size_t)b * Ntok * Cch + t;
    int wb = half * 32;
    bool rok[3];
    const float* xr[3];
#pragma unroll
    for (int r = 0; r < 3; r++) {
        int yy = hh - 1 + r;
        rok[r] = (yy >= 0 && yy < HRES);
        xr[r] = xb + (size_t)(rok[r] ? yy : 0) * rowStride;
    }

    float* orow = out + ((size_t)b * Ntok + n0) * Cch + t;

#pragma unroll
    for (int ch = 0; ch < 4; ch++) {
        int base = wb + ch * 8;
        float v[3][10];
#pragma unroll
        for (int r = 0; r < 3; r++)
#pragma unroll
            for (int j = 0; j < 10; j++) {
                int col = base - 1 + j;
                bool ok = rok[r] && col >= 0 && col < HRES;
                v[r][j] = ok ? xr[r][(size_t)col * Cch] : 0.f;
            }
#pragma unroll
        for (int w = 0; w < 8; w++) {
            float lp = lb;
#pragma unroll
            for (int r = 0; r < 3; r++)
                lp += v[r][w] * wl[r * 3 + 0] + v[r][w + 1] * wl[r * 3 + 1]
                    + v[r][w + 2] * wl[r * 3 + 2];
            int wcol = ch * 8 + w;
            orow[(size_t)wcol * Cch] = lp + O[wcol * FO_STRIDE + t];
        }
    }
}

// ---------------------------------------------------------------------------
extern "C" void kernel_launch(void* const* d_in, const int* in_sizes, int n_in,
                              void* d_out, int out_size)
{
    const float* x      = (const float*)d_in[0];
    const float* qk_w   = (const float*)d_in[1];
    const float* qk_b   = (const float*)d_in[2];
    const float* lepe_w = (const float*)d_in[3];
    const float* lepe_b = (const float*)d_in[4];
    float* out = (float*)d_out;

    cudaFuncSetAttribute(gemm_rope_tc, cudaFuncAttributeMaxDynamicSharedMemorySize, GEMM_SMEM);
    cudaFuncSetAttribute(finalize_kernel, cudaFuncAttributeMaxDynamicSharedMemorySize, FIN_SMEM);

    setup_kernel<<<SB_W, 256>>>(x, qk_w);
    gemm_rope_tc<<<dim3(TWOC / BN, (Bsz * Ntok) / BM), 256, GEMM_SMEM>>>(qk_b);
    kv_kernel<<<dim3(Bsz, NH / 4, KVSPLIT), 256>>>();
    finalize_kernel<<<dim3(HRES, 2, Bsz), 384, FIN_SMEM>>>(x, lepe_w, lepe_b, out);
}

// round 13
// speedup vs baseline: 1.0046x; 1.0046x over previous
#include <cuda_runtime.h>
#include <cuda_bf16.h>
#include <cstdint>

#define Bsz 16
#define Ntok 4096
#define Cch 384
#define HRES 64
#define NH 12
#define DH 32
#define TWOC 768

// Scratch (device globals: allocation-free rule)
__device__ __nv_bfloat16 g_xbf[Bsz * Ntok * Cch];   // bf16 copy of x
__device__ __nv_bfloat16 g_wbf[TWOC * Cch];         // bf16 copy of qk_w
__device__ __nv_bfloat16 g_qrb[Bsz * Ntok * Cch];   // roped q (bf16)
__device__ __nv_bfloat16 g_krb[Bsz * Ntok * Cch];   // roped k (bf16)
__device__ float  g_ksum[Bsz * Cch];                // sum_n k (unroped, fp32)
__device__ float  g_kv  [Bsz * NH * DH * DH];
__device__ float2 g_rope[Ntok * (Cch / 2)];

// ---------------------------------------------------------------------------
__device__ __forceinline__ uint32_t packbf(float a, float b) {
    __nv_bfloat162 h = __float22bfloat162_rn(make_float2(a, b));
    return *reinterpret_cast<uint32_t*>(&h);
}

__device__ __forceinline__ void ldm_x4(uint32_t* d, uint32_t addr) {
    asm volatile("ldmatrix.sync.aligned.m8n8.x4.shared.b16 {%0,%1,%2,%3}, [%4];"
                 : "=r"(d[0]), "=r"(d[1]), "=r"(d[2]), "=r"(d[3]) : "r"(addr));
}

__device__ __forceinline__ void mma16(float4& d, const uint32_t* a,
                                      uint32_t b0, uint32_t b1) {
    asm volatile(
        "mma.sync.aligned.m16n8k16.row.col.f32.bf16.bf16.f32 "
        "{%0,%1,%2,%3},{%4,%5,%6,%7},{%8,%9},{%0,%1,%2,%3};\n"
        : "+f"(d.x), "+f"(d.y), "+f"(d.z), "+f"(d.w)
        : "r"(a[0]), "r"(a[1]), "r"(a[2]), "r"(a[3]), "r"(b0), "r"(b1));
}

__device__ __forceinline__ void cp16(uint32_t smem, const void* g) {
    asm volatile("cp.async.cg.shared.global [%0], [%1], 16;" :: "r"(smem), "l"(g));
}

// ---------------------------------------------------------------------------
// Fused setup: rope table + zero scratch + bf16 conversion, one launch.
// ---------------------------------------------------------------------------
#define SB_ROPE 3072
#define SB_ZERO (SB_ROPE + 768)
#define SB_X    (SB_ZERO + 12288)
#define SB_W    (SB_X + 144)

__global__ __launch_bounds__(256) void setup_kernel(
    const float* __restrict__ x, const float* __restrict__ w)
{
    int blk = blockIdx.x;
    if (blk < SB_ROPE) {
        int i = blk * 256 + threadIdx.x;      // < 786432
        int n = i / 192, p = i % 192;
        int hh = n >> 6, ww = n & 63;
        int j = (p < 96) ? p : (p - 96);
        float theta = __expf(-((float)j * (1.0f / 96.0f)) * 9.210340371976184f);
        float pos = (p < 96) ? (float)hh : (float)ww;
        float s, c;
        sincosf(pos * theta, &s, &c);
        g_rope[(size_t)n * 192 + p] = make_float2(c, s);
    } else if (blk < SB_ZERO) {
        int i = (blk - SB_ROPE) * 256 + threadIdx.x;   // < 196608
        if (i < Bsz * Cch) g_ksum[i] = 0.f;
        g_kv[i] = 0.f;
    } else if (blk < SB_X) {
        size_t o = ((size_t)(blk - SB_ZERO) * 256 + threadIdx.x) * 8;
        float4 a = *(const float4*)(x + o);
        float4 b = *(const float4*)(x + o + 4);
        uint4 u = make_uint4(packbf(a.x, a.y), packbf(a.z, a.w),
                             packbf(b.x, b.y), packbf(b.z, b.w));
        *(uint4*)&g_xbf[o] = u;
    } else {
        size_t o = ((size_t)(blk - SB_X) * 256 + threadIdx.x) * 8;
        if (o < (size_t)TWOC * Cch) {
            float4 a = *(const float4*)(w + o);
            float4 b = *(const float4*)(w + o + 4);
            uint4 u = make_uint4(packbf(a.x, a.y), packbf(a.z, a.w),
                                 packbf(b.x, b.y), packbf(b.z, b.w));
            *(uint4*)&g_wbf[o] = u;
        }
    }
}

// ---------------------------------------------------------------------------
// GEMM qk = x @ W^T + b via bf16 MMA, cp.async 3-stage pipeline (R11 version).
// BM=128 BN=128 BK=32, 256 threads (8 warps: 2 in M x 4 in N), warp 64x32.
// jOff selects the j-block window: Q half = jOff 0, K half = jOff 3 (3 blocks).
// ---------------------------------------------------------------------------
#define BM 128
#define BN 128
#define BK 32
#define STAGES 3
#define NKT (Cch / BK)          // 12
#define AROW 80                  // bytes per smem row (40 bf16)
#define ATILE (BM * AROW)        // 10240
#define WTILE (BN * AROW)        // 10240
#define GEMM_SMEM (STAGES * (ATILE + WTILE))   // 61440

__global__ __launch_bounds__(256, 2) void gemm_rope_tc(const float* __restrict__ bias,
                                                       int jOff)
{
    extern __shared__ __align__(16) uint8_t gsm[];
    uint8_t* smA = gsm;
    uint8_t* smW = gsm + STAGES * ATILE;

    int tid  = threadIdx.x;
    int warp = tid >> 5, lane = tid & 31;
    int wm = warp >> 2, wn = warp & 3;
    int g  = lane >> 2, l4 = lane & 3;
    int r8 = lane & 7,  qq = lane >> 3;

    int jBase = (blockIdx.x + jOff) * BN;
    int mBase = blockIdx.y * BM;

    const __nv_bfloat16* xblk = g_xbf + (size_t)mBase * Cch;
    const __nv_bfloat16* wblk = g_wbf + (size_t)jBase * Cch;

    int am[2], ak[2];
#pragma unroll
    for (int i = 0; i < 2; i++) { int idx = tid + i * 256; am[i] = idx >> 2; ak[i] = (idx & 3) * 8; }

    uint32_t aBase = (uint32_t)__cvta_generic_to_shared(smA);
    uint32_t wBase = (uint32_t)__cvta_generic_to_shared(smW);
    uint32_t aOff = (uint32_t)(((qq & 1) * 8 + r8) * AROW + (qq >> 1) * 16);
    uint32_t bOff = (uint32_t)(((qq >> 1) * 8 + r8) * AROW + (qq & 1) * 16);

    auto loadTile = [&](int t, int buf) {
        int k0 = t * BK;
#pragma unroll
        for (int i = 0; i < 2; i++) {
            cp16(aBase + (uint32_t)(buf * ATILE + am[i] * AROW + ak[i] * 2),
                 xblk + (size_t)am[i] * Cch + k0 + ak[i]);
            cp16(wBase + (uint32_t)(buf * WTILE + am[i] * AROW + ak[i] * 2),
                 wblk + (size_t)am[i] * Cch + k0 + ak[i]);
        }
        asm volatile("cp.async.commit_group;");
    };

    float4 c[4][4];
#pragma unroll
    for (int i = 0; i < 4; i++)
#pragma unroll
        for (int f = 0; f < 4; f++) c[i][f] = make_float4(0.f, 0.f, 0.f, 0.f);

    loadTile(0, 0);
    loadTile(1, 1);

    for (int t = 0; t < NKT; t++) {
        asm volatile("cp.async.wait_group 1;");
        __syncthreads();
        if (t + 2 < NKT) loadTile(t + 2, (t + 2) % STAGES);

        int buf = t % STAGES;
        uint32_t aT = aBase + (uint32_t)(buf * ATILE);
        uint32_t wT = wBase + (uint32_t)(buf * WTILE);
#pragma unroll
        for (int kk = 0; kk < BK; kk += 16) {
            uint32_t a[4][4], b[2][4];
#pragma unroll
            for (int mi = 0; mi < 4; mi++)
                ldm_x4(a[mi], aT + (uint32_t)((wm * 64 + mi * 16) * AROW + kk * 2) + aOff);
#pragma unroll
            for (int bg = 0; bg < 2; bg++)
                ldm_x4(b[bg], wT + (uint32_t)((wn * 32 + bg * 16) * AROW + kk * 2) + bOff);
#pragma unroll
            for (int mi = 0; mi < 4; mi++)
#pragma unroll
                for (int bg = 0; bg < 2; bg++) {
                    mma16(c[mi][bg * 2],     a[mi], b[bg][0], b[bg][1]);
                    mma16(c[mi][bg * 2 + 1], a[mi], b[bg][2], b[bg][3]);
                }
        }
    }

    // ---- fused epilogue: bias, elu+1, RoPE, k-sum; bf16 outputs ----
    bool isK = (jBase >= Cch);
    int bb = mBase >> 12;
    float ksum_loc[4][2];
#pragma unroll
    for (int f = 0; f < 4; f++) { ksum_loc[f][0] = 0.f; ksum_loc[f][1] = 0.f; }

#pragma unroll
    for (int mi = 0; mi < 4; mi++) {
        int mrow0 = mBase + wm * 64 + mi * 16 + g;
#pragma unroll
        for (int f = 0; f < 4; f++) {
            int j0 = jBase + wn * 32 + f * 8 + 2 * l4;
            int jm = isK ? (j0 - Cch) : j0;
            float b0 = bias[j0], b1 = bias[j0 + 1];
#pragma unroll
            for (int rr = 0; rr < 2; rr++) {
                int m = mrow0 + rr * 8;
                float re = (rr == 0 ? c[mi][f].x : c[mi][f].z) + b0;
                float im = (rr == 0 ? c[mi][f].y : c[mi][f].w) + b1;
                re = (re > 0.f) ? (re + 1.f) : __expf(re);
                im = (im > 0.f) ? (im + 1.f) : __expf(im);
                int n = m & (Ntok - 1);
                float2 cs = g_rope[(size_t)n * 192 + (jm >> 1)];
                float rre = cs.x * re - cs.y * im;
                float rim = cs.y * re + cs.x * im;
                size_t off = (size_t)m * Cch + jm;
                uint32_t pk = packbf(rre, rim);
                if (!isK) {
                    *(uint32_t*)&g_qrb[off] = pk;
                } else {
                    *(uint32_t*)&g_krb[off] = pk;
                    ksum_loc[f][0] += re;
                    ksum_loc[f][1] += im;
                }
            }
        }
    }

    if (isK) {
#pragma unroll
        for (int f = 0; f < 4; f++) {
#pragma unroll
            for (int e = 0; e < 2; e++) {
                float v = ksum_loc[f][e];
                v += __shfl_xor_sync(0xffffffffu, v, 4);
                v += __shfl_xor_sync(0xffffffffu, v, 8);
                v += __shfl_xor_sync(0xffffffffu, v, 16);
                if (g == 0) {
                    int jm = (jBase - Cch) + wn * 32 + f * 8 + 2 * l4 + e;
                    atomicAdd(&g_ksum[bb * Cch + jm], v);
                }
            }
        }
    }
}

// ---------------------------------------------------------------------------
// kv[b][h] += (1/N) sum_n outer(k_rope, v);  bf16 inputs, fp32 accumulate.
// ---------------------------------------------------------------------------
#define KVCH 32
#define KVSPLIT 32
#define KVROW 256
#define KVTILE (KVCH * KVROW)

__global__ __launch_bounds__(256) void kv_kernel()
{
    int b = blockIdx.x, hq = blockIdx.y, s = blockIdx.z;
    int tid = threadIdx.x;
    __shared__ __align__(16) uint8_t ksm[2 * KVTILE];
    __shared__ __align__(16) uint8_t vsm[2 * KVTILE];

    int sub = tid >> 6;
    int st  = tid & 63;
    int d0  = (st >> 3) * 4;
    int e0  = (st & 7) * 4;

    float a[4][4];
#pragma unroll
    for (int r = 0; r < 4; r++)
#pragma unroll
        for (int cc = 0; cc < 4; cc++) a[r][cc] = 0.f;

    const int CHUNK = Ntok / KVSPLIT;
    const int NSTG  = CHUNK / KVCH;
    int nBase = s * CHUNK;
    const __nv_bfloat16* kr = g_krb + ((size_t)b * Ntok + nBase) * Cch + hq * 128;
    const __nv_bfloat16* vv = g_xbf + ((size_t)b * Ntok + nBase) * Cch + hq * 128;

    int ln[2], lc[2];
#pragma unroll
    for (int i = 0; i < 2; i++) { int idx = tid + i * 256; ln[i] = idx >> 4; lc[i] = (idx & 15) * 8; }
    uint32_t ksB = (uint32_t)__cvta_generic_to_shared(ksm);
    uint32_t vsB = (uint32_t)__cvta_generic_to_shared(vsm);

    auto load_stage = [&](int stg, int buf) {
#pragma unroll
        for (int i = 0; i < 2; i++) {
            uint32_t so = (uint32_t)(buf * KVTILE + ln[i] * KVROW + lc[i] * 2);
            size_t go = (size_t)(stg * KVCH + ln[i]) * Cch + lc[i];
            cp16(ksB + so, kr + go);
            cp16(vsB + so, vv + go);
        }
        asm volatile("cp.async.commit_group;");
    };

    load_stage(0, 0);
    for (int stg = 0; stg < NSTG; stg++) {
        if (stg + 1 < NSTG) {
            load_stage(stg + 1, (stg + 1) & 1);
            asm volatile("cp.async.wait_group 1;");
        } else {
            asm volatile("cp.async.wait_group 0;");
        }
        __syncthreads();
        int buf = stg & 1;
        const uint8_t* kb = ksm + buf * KVTILE + (sub * 32 + d0) * 2;
        const uint8_t* vb = vsm + buf * KVTILE + (sub * 32 + e0) * 2;
#pragma unroll
        for (int n = 0; n < KVCH; n++) {
            const __nv_bfloat162* kp = (const __nv_bfloat162*)(kb + n * KVROW);
            const __nv_bfloat162* vp = (const __nv_bfloat162*)(vb + n * KVROW);
            float2 k01 = __bfloat1622float2(kp[0]);
            float2 k23 = __bfloat1622float2(kp[1]);
            float2 v01 = __bfloat1622float2(vp[0]);
            float2 v23 = __bfloat1622float2(vp[1]);
            float kk[4] = {k01.x, k01.y, k23.x, k23.y};
            float vr[4] = {v01.x, v01.y, v23.x, v23.y};
#pragma unroll
            for (int r = 0; r < 4; r++)
#pragma unroll
                for (int cc = 0; cc < 4; cc++) a[r][cc] += kk[r] * vr[cc];
        }
        __syncthreads();
    }

    const float inv = 1.0f / (float)Ntok;
    float* dst = g_kv + (size_t)(b * NH + hq * 4 + sub) * DH * DH;
#pragma unroll
    for (int r = 0; r < 4; r++)
#pragma unroll
        for (int cc = 0; cc < 4; cc++)
            atomicAdd(&dst[(d0 + r) * DH + e0 + cc], a[r][cc] * inv);
}

// ---------------------------------------------------------------------------
// Finalize: tensor-core attention epilogue + chunked depthwise conv (fp32 x).
// SMEM UNION (57KB) + __launch_bounds__(384,3): 3 blocks/SM.
// ---------------------------------------------------------------------------
#define FQ_BYTES 784
#define FQ_SIZE  (32 * FQ_BYTES)            // 25088
#define FB_OFF   FQ_SIZE
#define FB_SIZE  (NH * DH * 80)             // 30720
#define FO_STRIDE 388
#define FO_SIZE  (32 * FO_STRIDE * 4)       // 49664  (< FQ_SIZE + FB_SIZE)
#define FZ_OFF   (FQ_SIZE + FB_SIZE)        // 55808
#define FIN_SMEM (FZ_OFF + NH * 32 * 4)     // 57344

__global__ __launch_bounds__(384, 3) void finalize_kernel(
    const float* __restrict__ x, const float* __restrict__ lepe_w,
    const float* __restrict__ lepe_b, float* __restrict__ out)
{
    extern __shared__ __align__(16) uint8_t fsm[];
    __nv_bfloat16* Q = (__nv_bfloat16*)fsm;
    uint8_t* Bkv = fsm + FB_OFF;
    float* O  = (float*)fsm;                 // union: valid after MMA+sync
    float* zs = (float*)(fsm + FZ_OFF);

    int hh = blockIdx.x, half = blockIdx.y, b = blockIdx.z;
    int t = threadIdx.x;
    int h = t >> 5, lane = t & 31;
    bool even = ((lane & 1) == 0);
    int n0 = hh * HRES + half * 32;

    uint32_t qB = (uint32_t)__cvta_generic_to_shared(Q);

    {
        const __nv_bfloat16* qsrc = g_qrb + ((size_t)b * Ntok + n0) * Cch;
#pragma unroll
        for (int i = 0; i < 4; i++) {
            int idx = i * 384 + t;
            int row = idx / 48, col = idx % 48;
            cp16(qB + (uint32_t)(row * FQ_BYTES + col * 16),
                 qsrc + (size_t)row * Cch + col * 8);
        }
        asm volatile("cp.async.commit_group;");
    }

    float km  = g_ksum[b * Cch + t] * (1.0f / (float)Ntok);
    float kmp = __shfl_xor_sync(0xffffffffu, km, 1);

    {
        const float* kvh = g_kv + (size_t)(b * NH + h) * DH * DH;
        __nv_bfloat16* Bh = (__nv_bfloat16*)(Bkv + h * (DH * 80));
#pragma unroll
        for (int d = 0; d < DH; d++) {
            float v = kvh[d * DH + lane];
            Bh[lane * 40 + d] = __float2bfloat16(v);
        }
    }

    asm volatile("cp.async.wait_group 0;");
    __syncthreads();

#pragma unroll 4
    for (int w = 0; w < 32; w++) {
        float2 cs = g_rope[(size_t)(n0 + w) * 192 + (h * 16 + (lane >> 1))];
        float qv = __bfloat162float(Q[w * 392 + h * 32 + lane]);
        float rkm = even ? (cs.x * km - cs.y * kmp) : (cs.y * kmp + cs.x * km);
        float prod = qv * rkm;
#pragma unroll
        for (int o = 16; o > 0; o >>= 1)
            prod += __shfl_xor_sync(0xffffffffu, prod, o);
        if (lane == 0) zs[h * 32 + w] = 1.0f / (prod + 1e-6f);
    }
    __syncwarp();

    float4 c[2][4];
#pragma unroll
    for (int i = 0; i < 2; i++)
#pragma unroll
        for (int f = 0; f < 4; f++) c[i][f] = make_float4(0.f, 0.f, 0.f, 0.f);
    {
        int qq = lane >> 3, r8 = lane & 7;
        uint32_t aOff = (uint32_t)(((qq & 1) * 8 + r8) * FQ_BYTES + (qq >> 1) * 16);
        uint32_t bOff = (uint32_t)(((qq >> 1) * 8 + r8) * 80 + (qq & 1) * 16);
        uint32_t bB = (uint32_t)__cvta_generic_to_shared(Bkv) + (uint32_t)(h * DH * 80);
#pragma unroll
        for (int kk = 0; kk < 32; kk += 16) {
            uint32_t a[2][4], bb[2][4];
#pragma unroll
            for (int tf = 0; tf < 2; tf++)
                ldm_x4(a[tf], qB + (uint32_t)(tf * 16 * FQ_BYTES + (h * 32 + kk) * 2) + aOff);
#pragma unroll
            for (int bg = 0; bg < 2; bg++)
                ldm_x4(bb[bg], bB + (uint32_t)(bg * 16 * 80 + kk * 2) + bOff);
#pragma unroll
            for (int tf = 0; tf < 2; tf++)
#pragma unroll
                for (int bg = 0; bg < 2; bg++) {
                    mma16(c[tf][bg * 2],     a[tf], bb[bg][0], bb[bg][1]);
                    mma16(c[tf][bg * 2 + 1], a[tf], bb[bg][2], bb[bg][3]);
                }
        }
    }

    // Phase boundary: Q/Bkv dead, O takes over the same smem.
    __syncthreads();

    {
        int g = lane >> 2, l4 = lane & 3;
#pragma unroll
        for (int tf = 0; tf < 2; tf++) {
            float zlo = zs[h * 32 + tf * 16 + g];
            float zhi = zs[h * 32 + tf * 16 + g + 8];
#pragma unroll
            for (int f = 0; f < 4; f++) {
                int e = h * 32 + f * 8 + 2 * l4;
                float* lo = &O[(tf * 16 + g) * FO_STRIDE + e];
                float* hi = &O[(tf * 16 + g + 8) * FO_STRIDE + e];
                lo[0] = c[tf][f].x * zlo;  lo[1] = c[tf][f].y * zlo;
                hi[0] = c[tf][f].z * zhi;  hi[1] = c[tf][f].w * zhi;
            }
        }
    }
    __syncthreads();

    // Phase 4: chunked depthwise 3x3 conv (fp32 x) + add O
    float wl[9];
#pragma unroll
    for (int i = 0; i < 9; i++) wl[i] = lepe_w[t * 9 + i];
    float lb = lepe_b[t];

    const size_t rowStride = (size_t)HRES * Cch;
    const float* xb = x + (size_t)b * Ntok * Cch + t;
    int wb = half * 32;
    bool rok[3];
    const float* xr[3];
#pragma unroll
    for (int r = 0; r < 3; r++) {
        int yy = hh - 1 + r;
        rok[r] = (yy >= 0 && yy < HRES);
        xr[r] = xb + (size_t)(rok[r] ? yy : 0) * rowStride;
    }

    float* orow = out + ((size_t)b * Ntok + n0) * Cch + t;

#pragma unroll
    for (int ch = 0; ch < 4; ch++) {
        int base = wb + ch * 8;
        float v[3][10];
#pragma unroll
        for (int r = 0; r < 3; r++)
#pragma unroll
            for (int j = 0; j < 10; j++) {
                int col = base - 1 + j;
                bool ok = rok[r] && col >= 0 && col < HRES;
                v[r][j] = ok ? xr[r][(size_t)col * Cch] : 0.f;
            }
#pragma unroll
        for (int w = 0; w < 8; w++) {
            float lp = lb;
#pragma unroll
            for (int r = 0; r < 3; r++)
                lp += v[r][w] * wl[r * 3 + 0] + v[r][w + 1] * wl[r * 3 + 1]
                    + v[r][w + 2] * wl[r * 3 + 2];
            int wcol = ch * 8 + w;
            orow[(size_t)wcol * Cch] = lp + O[wcol * FO_STRIDE + t];
        }
    }
}

// ---------------------------------------------------------------------------
extern "C" void kernel_launch(void* const* d_in, const int* in_sizes, int n_in,
                              void* d_out, int out_size)
{
    const float* x      = (const float*)d_in[0];
    const float* qk_w   = (const float*)d_in[1];
    const float* qk_b   = (const float*)d_in[2];
    const float* lepe_w = (const float*)d_in[3];
    const float* lepe_b = (const float*)d_in[4];
    float* out = (float*)d_out;

    static bool init = false;
    static cudaStream_t s2;
    static cudaEvent_t evK, evKV;
    if (!init) {
        cudaFuncSetAttribute(gemm_rope_tc, cudaFuncAttributeMaxDynamicSharedMemorySize, GEMM_SMEM);
        cudaFuncSetAttribute(finalize_kernel, cudaFuncAttributeMaxDynamicSharedMemorySize, FIN_SMEM);
        cudaStreamCreateWithFlags(&s2, cudaStreamNonBlocking);
        cudaEventCreateWithFlags(&evK,  cudaEventDisableTiming);
        cudaEventCreateWithFlags(&evKV, cudaEventDisableTiming);
        init = true;
    }

    setup_kernel<<<SB_W, 256>>>(x, qk_w);
    // K-half of the GEMM first (j-blocks 3..5): produces g_krb + g_ksum.
    gemm_rope_tc<<<dim3(3, (Bsz * Ntok) / BM), 256, GEMM_SMEM>>>(qk_b, 3);
    cudaEventRecord(evK, 0);
    // Fork: kv on stream s2, overlapping the Q-half GEMM on stream 0.
    cudaStreamWaitEvent(s2, evK, 0);
    kv_kernel<<<dim3(Bsz, NH / 4, KVSPLIT), 256, 0, s2>>>();
    cudaEventRecord(evKV, s2);
    // Q-half of the GEMM (j-blocks 0..2): produces g_qrb.
    gemm_rope_tc<<<dim3(3, (Bsz * Ntok) / BM), 256, GEMM_SMEM>>>(qk_b, 0);
    // Join: finalize needs kv + qrb + ksum.
    cudaStreamWaitEvent(0, evKV, 0);
    finalize_kernel<<<dim3(HRES, 2, Bsz), 384, FIN_SMEM>>>(x, lepe_w, lepe_b, out);
}

// round 14
// speedup vs baseline: 1.0122x; 1.0076x over previous
#include <cuda_runtime.h>
#include <cuda_bf16.h>
#include <cstdint>

#define Bsz 16
#define Ntok 4096
#define Cch 384
#define HRES 64
#define NH 12
#define DH 32
#define TWOC 768

// Scratch (device globals: allocation-free rule)
__device__ __nv_bfloat16 g_xbf[Bsz * Ntok * Cch];   // bf16 copy of x
__device__ __nv_bfloat16 g_wbf[TWOC * Cch];         // bf16 copy of qk_w
__device__ __nv_bfloat16 g_qrb[Bsz * Ntok * Cch];   // roped q (bf16)
__device__ __nv_bfloat16 g_krb[Bsz * Ntok * Cch];   // roped k (bf16)
__device__ float  g_ksum[Bsz * Cch];                // sum_n k (unroped, fp32)
__device__ float  g_kv  [Bsz * NH * DH * DH];
__device__ float2 g_rope[Ntok * (Cch / 2)];

// ---------------------------------------------------------------------------
__device__ __forceinline__ uint32_t packbf(float a, float b) {
    __nv_bfloat162 h = __float22bfloat162_rn(make_float2(a, b));
    return *reinterpret_cast<uint32_t*>(&h);
}

__device__ __forceinline__ void ldm_x4(uint32_t* d, uint32_t addr) {
    asm volatile("ldmatrix.sync.aligned.m8n8.x4.shared.b16 {%0,%1,%2,%3}, [%4];"
                 : "=r"(d[0]), "=r"(d[1]), "=r"(d[2]), "=r"(d[3]) : "r"(addr));
}

__device__ __forceinline__ void mma16(float4& d, const uint32_t* a,
                                      uint32_t b0, uint32_t b1) {
    asm volatile(
        "mma.sync.aligned.m16n8k16.row.col.f32.bf16.bf16.f32 "
        "{%0,%1,%2,%3},{%4,%5,%6,%7},{%8,%9},{%0,%1,%2,%3};\n"
        : "+f"(d.x), "+f"(d.y), "+f"(d.z), "+f"(d.w)
        : "r"(a[0]), "r"(a[1]), "r"(a[2]), "r"(a[3]), "r"(b0), "r"(b1));
}

__device__ __forceinline__ void cp16(uint32_t smem, const void* g) {
    asm volatile("cp.async.cg.shared.global [%0], [%1], 16;" :: "r"(smem), "l"(g));
}

// ---------------------------------------------------------------------------
// Fused setup: rope table + zero scratch + bf16 conversion, one launch.
// ---------------------------------------------------------------------------
#define SB_ROPE 3072
#define SB_ZERO (SB_ROPE + 768)
#define SB_X    (SB_ZERO + 12288)
#define SB_W    (SB_X + 144)

__global__ __launch_bounds__(256) void setup_kernel(
    const float* __restrict__ x, const float* __restrict__ w)
{
    int blk = blockIdx.x;
    if (blk < SB_ROPE) {
        int i = blk * 256 + threadIdx.x;      // < 786432
        int n = i / 192, p = i % 192;
        int hh = n >> 6, ww = n & 63;
        int j = (p < 96) ? p : (p - 96);
        float theta = __expf(-((float)j * (1.0f / 96.0f)) * 9.210340371976184f);
        float pos = (p < 96) ? (float)hh : (float)ww;
        float s, c;
        sincosf(pos * theta, &s, &c);
        g_rope[(size_t)n * 192 + p] = make_float2(c, s);
    } else if (blk < SB_ZERO) {
        int i = (blk - SB_ROPE) * 256 + threadIdx.x;   // < 196608
        if (i < Bsz * Cch) g_ksum[i] = 0.f;
        g_kv[i] = 0.f;
    } else if (blk < SB_X) {
        size_t o = ((size_t)(blk - SB_ZERO) * 256 + threadIdx.x) * 8;
        float4 a = *(const float4*)(x + o);
        float4 b = *(const float4*)(x + o + 4);
        uint4 u = make_uint4(packbf(a.x, a.y), packbf(a.z, a.w),
                             packbf(b.x, b.y), packbf(b.z, b.w));
        *(uint4*)&g_xbf[o] = u;
    } else {
        size_t o = ((size_t)(blk - SB_X) * 256 + threadIdx.x) * 8;
        if (o < (size_t)TWOC * Cch) {
            float4 a = *(const float4*)(w + o);
            float4 b = *(const float4*)(w + o + 4);
            uint4 u = make_uint4(packbf(a.x, a.y), packbf(a.z, a.w),
                                 packbf(b.x, b.y), packbf(b.z, b.w));
            *(uint4*)&g_wbf[o] = u;
        }
    }
}

// ---------------------------------------------------------------------------
// GEMM qk = x @ W^T + b via bf16 MMA, cp.async 4-stage pipeline.
// BM=128 BN=128 BK=32, 256 threads (8 warps: 2 in M x 4 in N), warp 64x32.
// grid (6 j-blocks fast, 512 m-blocks).
// ---------------------------------------------------------------------------
#define BM 128
#define BN 128
#define BK 32
#define STAGES 4
#define NKT (Cch / BK)          // 12
#define AROW 80                  // bytes per smem row (40 bf16)
#define ATILE (BM * AROW)        // 10240
#define WTILE (BN * AROW)        // 10240
#define GEMM_SMEM (STAGES * (ATILE + WTILE))   // 81920

__global__ __launch_bounds__(256, 2) void gemm_rope_tc(const float* __restrict__ bias)
{
    extern __shared__ __align__(16) uint8_t gsm[];
    uint8_t* smA = gsm;
    uint8_t* smW = gsm + STAGES * ATILE;

    int tid  = threadIdx.x;
    int warp = tid >> 5, lane = tid & 31;
    int wm = warp >> 2, wn = warp & 3;
    int g  = lane >> 2, l4 = lane & 3;
    int r8 = lane & 7,  qq = lane >> 3;

    int jBase = blockIdx.x * BN;
    int mBase = blockIdx.y * BM;

    const __nv_bfloat16* xblk = g_xbf + (size_t)mBase * Cch;
    const __nv_bfloat16* wblk = g_wbf + (size_t)jBase * Cch;

    int am[2], ak[2];
#pragma unroll
    for (int i = 0; i < 2; i++) { int idx = tid + i * 256; am[i] = idx >> 2; ak[i] = (idx & 3) * 8; }

    uint32_t aBase = (uint32_t)__cvta_generic_to_shared(smA);
    uint32_t wBase = (uint32_t)__cvta_generic_to_shared(smW);
    uint32_t aOff = (uint32_t)(((qq & 1) * 8 + r8) * AROW + (qq >> 1) * 16);
    uint32_t bOff = (uint32_t)(((qq >> 1) * 8 + r8) * AROW + (qq & 1) * 16);

    auto loadTile = [&](int t, int buf) {
        int k0 = t * BK;
#pragma unroll
        for (int i = 0; i < 2; i++) {
            cp16(aBase + (uint32_t)(buf * ATILE + am[i] * AROW + ak[i] * 2),
                 xblk + (size_t)am[i] * Cch + k0 + ak[i]);
            cp16(wBase + (uint32_t)(buf * WTILE + am[i] * AROW + ak[i] * 2),
                 wblk + (size_t)am[i] * Cch + k0 + ak[i]);
        }
        asm volatile("cp.async.commit_group;");
    };

    float4 c[4][4];
#pragma unroll
    for (int i = 0; i < 4; i++)
#pragma unroll
        for (int f = 0; f < 4; f++) c[i][f] = make_float4(0.f, 0.f, 0.f, 0.f);

    loadTile(0, 0);
    loadTile(1, 1);
    loadTile(2, 2);

    for (int t = 0; t < NKT; t++) {
        asm volatile("cp.async.wait_group 2;");   // tile t done; t+1,t+2 in flight
        __syncthreads();
        if (t + 3 < NKT) loadTile(t + 3, (t + 3) % STAGES);

        int buf = t % STAGES;
        uint32_t aT = aBase + (uint32_t)(buf * ATILE);
        uint32_t wT = wBase + (uint32_t)(buf * WTILE);
#pragma unroll
        for (int kk = 0; kk < BK; kk += 16) {
            uint32_t a[4][4], b[2][4];
#pragma unroll
            for (int mi = 0; mi < 4; mi++)
                ldm_x4(a[mi], aT + (uint32_t)((wm * 64 + mi * 16) * AROW + kk * 2) + aOff);
#pragma unroll
            for (int bg = 0; bg < 2; bg++)
                ldm_x4(b[bg], wT + (uint32_t)((wn * 32 + bg * 16) * AROW + kk * 2) + bOff);
#pragma unroll
            for (int mi = 0; mi < 4; mi++)
#pragma unroll
                for (int bg = 0; bg < 2; bg++) {
                    mma16(c[mi][bg * 2],     a[mi], b[bg][0], b[bg][1]);
                    mma16(c[mi][bg * 2 + 1], a[mi], b[bg][2], b[bg][3]);
                }
        }
    }

    // ---- fused epilogue: bias, elu+1, RoPE, k-sum; bf16 outputs ----
    bool isK = (jBase >= Cch);
    int bb = mBase >> 12;
    float ksum_loc[4][2];
#pragma unroll
    for (int f = 0; f < 4; f++) { ksum_loc[f][0] = 0.f; ksum_loc[f][1] = 0.f; }

#pragma unroll
    for (int mi = 0; mi < 4; mi++) {
        int mrow0 = mBase + wm * 64 + mi * 16 + g;
#pragma unroll
        for (int f = 0; f < 4; f++) {
            int j0 = jBase + wn * 32 + f * 8 + 2 * l4;
            int jm = isK ? (j0 - Cch) : j0;
            float b0 = bias[j0], b1 = bias[j0 + 1];
#pragma unroll
            for (int rr = 0; rr < 2; rr++) {
                int m = mrow0 + rr * 8;
                float re = (rr == 0 ? c[mi][f].x : c[mi][f].z) + b0;
                float im = (rr == 0 ? c[mi][f].y : c[mi][f].w) + b1;
                re = (re > 0.f) ? (re + 1.f) : __expf(re);
                im = (im > 0.f) ? (im + 1.f) : __expf(im);
                int n = m & (Ntok - 1);
                float2 cs = g_rope[(size_t)n * 192 + (jm >> 1)];
                float rre = cs.x * re - cs.y * im;
                float rim = cs.y * re + cs.x * im;
                size_t off = (size_t)m * Cch + jm;
                uint32_t pk = packbf(rre, rim);
                if (!isK) {
                    *(uint32_t*)&g_qrb[off] = pk;
                } else {
                    *(uint32_t*)&g_krb[off] = pk;
                    ksum_loc[f][0] += re;
                    ksum_loc[f][1] += im;
                }
            }
        }
    }

    if (isK) {
#pragma unroll
        for (int f = 0; f < 4; f++) {
#pragma unroll
            for (int e = 0; e < 2; e++) {
                float v = ksum_loc[f][e];
                v += __shfl_xor_sync(0xffffffffu, v, 4);
                v += __shfl_xor_sync(0xffffffffu, v, 8);
                v += __shfl_xor_sync(0xffffffffu, v, 16);
                if (g == 0) {
                    int jm = (jBase - Cch) + wn * 32 + f * 8 + 2 * l4 + e;
                    atomicAdd(&g_ksum[bb * Cch + jm], v);
                }
            }
        }
    }
}

// ---------------------------------------------------------------------------
// kv[b][h] += (1/N) sum_n outer(k_rope, v);  bf16 inputs, fp32 accumulate.
// ---------------------------------------------------------------------------
#define KVCH 32
#define KVSPLIT 32
#define KVROW 256
#define KVTILE (KVCH * KVROW)

__global__ __launch_bounds__(256) void kv_kernel()
{
    int b = blockIdx.x, hq = blockIdx.y, s = blockIdx.z;
    int tid = threadIdx.x;
    __shared__ __align__(16) uint8_t ksm[2 * KVTILE];
    __shared__ __align__(16) uint8_t vsm[2 * KVTILE];

    int sub = tid >> 6;
    int st  = tid & 63;
    int d0  = (st >> 3) * 4;
    int e0  = (st & 7) * 4;

    float a[4][4];
#pragma unroll
    for (int r = 0; r < 4; r++)
#pragma unroll
        for (int cc = 0; cc < 4; cc++) a[r][cc] = 0.f;

    const int CHUNK = Ntok / KVSPLIT;
    const int NSTG  = CHUNK / KVCH;
    int nBase = s * CHUNK;
    const __nv_bfloat16* kr = g_krb + ((size_t)b * Ntok + nBase) * Cch + hq * 128;
    const __nv_bfloat16* vv = g_xbf + ((size_t)b * Ntok + nBase) * Cch + hq * 128;

    int ln[2], lc[2];
#pragma unroll
    for (int i = 0; i < 2; i++) { int idx = tid + i * 256; ln[i] = idx >> 4; lc[i] = (idx & 15) * 8; }
    uint32_t ksB = (uint32_t)__cvta_generic_to_shared(ksm);
    uint32_t vsB = (uint32_t)__cvta_generic_to_shared(vsm);

    auto load_stage = [&](int stg, int buf) {
#pragma unroll
        for (int i = 0; i < 2; i++) {
            uint32_t so = (uint32_t)(buf * KVTILE + ln[i] * KVROW + lc[i] * 2);
            size_t go = (size_t)(stg * KVCH + ln[i]) * Cch + lc[i];
            cp16(ksB + so, kr + go);
            cp16(vsB + so, vv + go);
        }
        asm volatile("cp.async.commit_group;");
    };

    load_stage(0, 0);
    for (int stg = 0; stg < NSTG; stg++) {
        if (stg + 1 < NSTG) {
            load_stage(stg + 1, (stg + 1) & 1);
            asm volatile("cp.async.wait_group 1;");
        } else {
            asm volatile("cp.async.wait_group 0;");
        }
        __syncthreads();
        int buf = stg & 1;
        const uint8_t* kb = ksm + buf * KVTILE + (sub * 32 + d0) * 2;
        const uint8_t* vb = vsm + buf * KVTILE + (sub * 32 + e0) * 2;
#pragma unroll
        for (int n = 0; n < KVCH; n++) {
            const __nv_bfloat162* kp = (const __nv_bfloat162*)(kb + n * KVROW);
            const __nv_bfloat162* vp = (const __nv_bfloat162*)(vb + n * KVROW);
            float2 k01 = __bfloat1622float2(kp[0]);
            float2 k23 = __bfloat1622float2(kp[1]);
            float2 v01 = __bfloat1622float2(vp[0]);
            float2 v23 = __bfloat1622float2(vp[1]);
            float kk[4] = {k01.x, k01.y, k23.x, k23.y};
            float vr[4] = {v01.x, v01.y, v23.x, v23.y};
#pragma unroll
            for (int r = 0; r < 4; r++)
#pragma unroll
                for (int cc = 0; cc < 4; cc++) a[r][cc] += kk[r] * vr[cc];
        }
        __syncthreads();
    }

    const float inv = 1.0f / (float)Ntok;
    float* dst = g_kv + (size_t)(b * NH + hq * 4 + sub) * DH * DH;
#pragma unroll
    for (int r = 0; r < 4; r++)
#pragma unroll
        for (int cc = 0; cc < 4; cc++)
            atomicAdd(&dst[(d0 + r) * DH + e0 + cc], a[r][cc] * inv);
}

// ---------------------------------------------------------------------------
// Finalize: tensor-core attention epilogue + chunked depthwise conv (fp32 x).
// SMEM UNION (57KB) + __launch_bounds__(384,3): 3 blocks/SM.
// z-phase: chunk-4 prefetch (rope + Q) to break the serial load->reduce chain.
// ---------------------------------------------------------------------------
#define FQ_BYTES 784
#define FQ_SIZE  (32 * FQ_BYTES)            // 25088
#define FB_OFF   FQ_SIZE
#define FB_SIZE  (NH * DH * 80)             // 30720
#define FO_STRIDE 388
#define FO_SIZE  (32 * FO_STRIDE * 4)       // 49664  (< FQ_SIZE + FB_SIZE)
#define FZ_OFF   (FQ_SIZE + FB_SIZE)        // 55808
#define FIN_SMEM (FZ_OFF + NH * 32 * 4)     // 57344

__global__ __launch_bounds__(384, 3) void finalize_kernel(
    const float* __restrict__ x, const float* __restrict__ lepe_w,
    const float* __restrict__ lepe_b, float* __restrict__ out)
{
    extern __shared__ __align__(16) uint8_t fsm[];
    __nv_bfloat16* Q = (__nv_bfloat16*)fsm;
    uint8_t* Bkv = fsm + FB_OFF;
    float* O  = (float*)fsm;                 // union: valid after MMA+sync
    float* zs = (float*)(fsm + FZ_OFF);

    int hh = blockIdx.x, half = blockIdx.y, b = blockIdx.z;
    int t = threadIdx.x;
    int h = t >> 5, lane = t & 31;
    bool even = ((lane & 1) == 0);
    int n0 = hh * HRES + half * 32;

    uint32_t qB = (uint32_t)__cvta_generic_to_shared(Q);

    {
        const __nv_bfloat16* qsrc = g_qrb + ((size_t)b * Ntok + n0) * Cch;
#pragma unroll
        for (int i = 0; i < 4; i++) {
            int idx = i * 384 + t;
            int row = idx / 48, col = idx % 48;
            cp16(qB + (uint32_t)(row * FQ_BYTES + col * 16),
                 qsrc + (size_t)row * Cch + col * 8);
        }
        asm volatile("cp.async.commit_group;");
    }

    float km  = g_ksum[b * Cch + t] * (1.0f / (float)Ntok);
    float kmp = __shfl_xor_sync(0xffffffffu, km, 1);

    {
        const float* kvh = g_kv + (size_t)(b * NH + h) * DH * DH;
        __nv_bfloat16* Bh = (__nv_bfloat16*)(Bkv + h * (DH * 80));
#pragma unroll
        for (int d = 0; d < DH; d++) {
            float v = kvh[d * DH + lane];
            Bh[lane * 40 + d] = __float2bfloat16(v);
        }
    }

    asm volatile("cp.async.wait_group 0;");
    __syncthreads();

    // z-phase: chunk-4 prefetched rope + Q, interleaved reduce chains
    {
        const float2* roperow = g_rope + (size_t)n0 * 192 + (h * 16 + (lane >> 1));
#pragma unroll
        for (int wq = 0; wq < 8; wq++) {
            float2 cs4[4];
            float  qv4[4];
#pragma unroll
            for (int i = 0; i < 4; i++) {
                int w = wq * 4 + i;
                cs4[i] = roperow[(size_t)w * 192];
                qv4[i] = __bfloat162float(Q[w * 392 + h * 32 + lane]);
            }
#pragma unroll
            for (int i = 0; i < 4; i++) {
                float rkm = even ? (cs4[i].x * km - cs4[i].y * kmp)
                                 : (cs4[i].y * kmp + cs4[i].x * km);
                float prod = qv4[i] * rkm;
#pragma unroll
                for (int o = 16; o > 0; o >>= 1)
                    prod += __shfl_xor_sync(0xffffffffu, prod, o);
                if (lane == 0) zs[h * 32 + wq * 4 + i] = 1.0f / (prod + 1e-6f);
            }
        }
    }
    __syncwarp();

    float4 c[2][4];
#pragma unroll
    for (int i = 0; i < 2; i++)
#pragma unroll
        for (int f = 0; f < 4; f++) c[i][f] = make_float4(0.f, 0.f, 0.f, 0.f);
    {
        int qq = lane >> 3, r8 = lane & 7;
        uint32_t aOff = (uint32_t)(((qq & 1) * 8 + r8) * FQ_BYTES + (qq >> 1) * 16);
        uint32_t bOff = (uint32_t)(((qq >> 1) * 8 + r8) * 80 + (qq & 1) * 16);
        uint32_t bB = (uint32_t)__cvta_generic_to_shared(Bkv) + (uint32_t)(h * DH * 80);
#pragma unroll
        for (int kk = 0; kk < 32; kk += 16) {
            uint32_t a[2][4], bb[2][4];
#pragma unroll
            for (int tf = 0; tf < 2; tf++)
                ldm_x4(a[tf], qB + (uint32_t)(tf * 16 * FQ_BYTES + (h * 32 + kk) * 2) + aOff);
#pragma unroll
            for (int bg = 0; bg < 2; bg++)
                ldm_x4(bb[bg], bB + (uint32_t)(bg * 16 * 80 + kk * 2) + bOff);
#pragma unroll
            for (int tf = 0; tf < 2; tf++)
#pragma unroll
                for (int bg = 0; bg < 2; bg++) {
                    mma16(c[tf][bg * 2],     a[tf], bb[bg][0], bb[bg][1]);
                    mma16(c[tf][bg * 2 + 1], a[tf], bb[bg][2], bb[bg][3]);
                }
        }
    }

    // Phase boundary: Q/Bkv dead, O takes over the same smem.
    __syncthreads();

    {
        int g = lane >> 2, l4 = lane & 3;
#pragma unroll
        for (int tf = 0; tf < 2; tf++) {
            float zlo = zs[h * 32 + tf * 16 + g];
            float zhi = zs[h * 32 + tf * 16 + g + 8];
#pragma unroll
            for (int f = 0; f < 4; f++) {
                int e = h * 32 + f * 8 + 2 * l4;
                float* lo = &O[(tf * 16 + g) * FO_STRIDE + e];
                float* hi = &O[(tf * 16 + g + 8) * FO_STRIDE + e];
                lo[0] = c[tf][f].x * zlo;  lo[1] = c[tf][f].y * zlo;
                hi[0] = c[tf][f].z * zhi;  hi[1] = c[tf][f].w * zhi;
            }
        }
    }
    __syncthreads();

    // Phase 4: chunked depthwise 3x3 conv (fp32 x) + add O
    float wl[9];
#pragma unroll
    for (int i = 0; i < 9; i++) wl[i] = lepe_w[t * 9 + i];
    float lb = lepe_b[t];

    const size_t rowStride = (size_t)HRES * Cch;
    const float* xb = x + (size_t)b * Ntok * Cch + t;
    int wb = half * 32;
    bool rok[3];
    const float* xr[3];
#pragma unroll
    for (int r = 0; r < 3; r++) {
        int yy = hh - 1 + r;
        rok[r] = (yy >= 0 && yy < HRES);
        xr[r] = xb + (size_t)(rok[r] ? yy : 0) * rowStride;
    }

    float* orow = out + ((size_t)b * Ntok + n0) * Cch + t;

#pragma unroll
    for (int ch = 0; ch < 4; ch++) {
        int base = wb + ch * 8;
        float v[3][10];
#pragma unroll
        for (int r = 0; r < 3; r++)
#pragma unroll
            for (int j = 0; j < 10; j++) {
                int col = base - 1 + j;
                bool ok = rok[r] && col >= 0 && col < HRES;
                v[r][j] = ok ? xr[r][(size_t)col * Cch] : 0.f;
            }
#pragma unroll
        for (int w = 0; w < 8; w++) {
            float lp = lb;
#pragma unroll
            for (int r = 0; r < 3; r++)
                lp += v[r][w] * wl[r * 3 + 0] + v[r][w + 1] * wl[r * 3 + 1]
                    + v[r][w + 2] * wl[r * 3 + 2];
            int wcol = ch * 8 + w;
            orow[(size_t)wcol * Cch] = lp + O[wcol * FO_STRIDE + t];
        }
    }
}

// ---------------------------------------------------------------------------
extern "C" void kernel_launch(void* const* d_in, const int* in_sizes, int n_in,
                              void* d_out, int out_size)
{
    const float* x      = (const float*)d_in[0];
    const float* qk_w   = (const float*)d_in[1];
    const float* qk_b   = (const float*)d_in[2];
    const float* lepe_w = (const float*)d_in[3];
    const float* lepe_b = (const float*)d_in[4];
    float* out = (float*)d_out;

    static bool init = false;
    if (!init) {
        cudaFuncSetAttribute(gemm_rope_tc, cudaFuncAttributeMaxDynamicSharedMemorySize, GEMM_SMEM);
        cudaFuncSetAttribute(finalize_kernel, cudaFuncAttributeMaxDynamicSharedMemorySize, FIN_SMEM);
        init = true;
    }

    setup_kernel<<<SB_W, 256>>>(x, qk_w);
    gemm_rope_tc<<<dim3(TWOC / BN, (Bsz * Ntok) / BM), 256, GEMM_SMEM>>>(qk_b);
    kv_kernel<<<dim3(Bsz, NH / 4, KVSPLIT), 256>>>();
    finalize_kernel<<<dim3(HRES, 2, Bsz), 384, FIN_SMEM>>>(x, lepe_w, lepe_b, out);
}

// round 15
// speedup vs baseline: 1.0760x; 1.0630x over previous
#include <cuda_runtime.h>
#include <cuda_bf16.h>
#include <cstdint>

#define Bsz 16
#define Ntok 4096
#define Cch 384
#define HRES 64
#define NH 12
#define DH 32
#define TWOC 768

// Scratch (device globals: allocation-free rule)
__device__ __nv_bfloat16 g_xbf[Bsz * Ntok * Cch];   // bf16 copy of x
__device__ __nv_bfloat16 g_wbf[TWOC * Cch];         // bf16 copy of qk_w
__device__ __nv_bfloat16 g_qrb[Bsz * Ntok * Cch];   // roped q (bf16)
__device__ __nv_bfloat16 g_krb[Bsz * Ntok * Cch];   // roped k (bf16)
__device__ float  g_ksum[Bsz * Cch];                // sum_n k (unroped, fp32)
__device__ float  g_kv  [Bsz * NH * DH * DH];
__device__ float2 g_rope[Ntok * (Cch / 2)];

// ---------------------------------------------------------------------------
__device__ __forceinline__ uint32_t packbf(float a, float b) {
    __nv_bfloat162 h = __float22bfloat162_rn(make_float2(a, b));
    return *reinterpret_cast<uint32_t*>(&h);
}

__device__ __forceinline__ void ldm_x4(uint32_t* d, uint32_t addr) {
    asm volatile("ldmatrix.sync.aligned.m8n8.x4.shared.b16 {%0,%1,%2,%3}, [%4];"
                 : "=r"(d[0]), "=r"(d[1]), "=r"(d[2]), "=r"(d[3]) : "r"(addr));
}

__device__ __forceinline__ void mma16(float4& d, const uint32_t* a,
                                      uint32_t b0, uint32_t b1) {
    asm volatile(
        "mma.sync.aligned.m16n8k16.row.col.f32.bf16.bf16.f32 "
        "{%0,%1,%2,%3},{%4,%5,%6,%7},{%8,%9},{%0,%1,%2,%3};\n"
        : "+f"(d.x), "+f"(d.y), "+f"(d.z), "+f"(d.w)
        : "r"(a[0]), "r"(a[1]), "r"(a[2]), "r"(a[3]), "r"(b0), "r"(b1));
}

__device__ __forceinline__ void cp16(uint32_t smem, const void* g) {
    asm volatile("cp.async.cg.shared.global [%0], [%1], 16;" :: "r"(smem), "l"(g));
}

// ---------------------------------------------------------------------------
// Fused setup: rope table + zero scratch + bf16 conversion, one launch.
// ---------------------------------------------------------------------------
#define SB_ROPE 3072
#define SB_ZERO (SB_ROPE + 768)
#define SB_X    (SB_ZERO + 12288)
#define SB_W    (SB_X + 144)

__global__ __launch_bounds__(256) void setup_kernel(
    const float* __restrict__ x, const float* __restrict__ w)
{
    int blk = blockIdx.x;
    if (blk < SB_ROPE) {
        int i = blk * 256 + threadIdx.x;      // < 786432
        int n = i / 192, p = i % 192;
        int hh = n >> 6, ww = n & 63;
        int j = (p < 96) ? p : (p - 96);
        float theta = __expf(-((float)j * (1.0f / 96.0f)) * 9.210340371976184f);
        float pos = (p < 96) ? (float)hh : (float)ww;
        float s, c;
        sincosf(pos * theta, &s, &c);
        g_rope[(size_t)n * 192 + p] = make_float2(c, s);
    } else if (blk < SB_ZERO) {
        int i = (blk - SB_ROPE) * 256 + threadIdx.x;   // < 196608
        if (i < Bsz * Cch) g_ksum[i] = 0.f;
        g_kv[i] = 0.f;
    } else if (blk < SB_X) {
        size_t o = ((size_t)(blk - SB_ZERO) * 256 + threadIdx.x) * 8;
        float4 a = *(const float4*)(x + o);
        float4 b = *(const float4*)(x + o + 4);
        uint4 u = make_uint4(packbf(a.x, a.y), packbf(a.z, a.w),
                             packbf(b.x, b.y), packbf(b.z, b.w));
        *(uint4*)&g_xbf[o] = u;
    } else {
        size_t o = ((size_t)(blk - SB_X) * 256 + threadIdx.x) * 8;
        if (o < (size_t)TWOC * Cch) {
            float4 a = *(const float4*)(w + o);
            float4 b = *(const float4*)(w + o + 4);
            uint4 u = make_uint4(packbf(a.x, a.y), packbf(a.z, a.w),
                                 packbf(b.x, b.y), packbf(b.z, b.w));
            *(uint4*)&g_wbf[o] = u;
        }
    }
}

// ---------------------------------------------------------------------------
// GEMM qk = x @ W^T + b via bf16 MMA, cp.async 3-stage pipeline (R11 proven).
// BM=128 BN=128 BK=32, 256 threads (8 warps: 2 in M x 4 in N), warp 64x32.
// grid (6 j-blocks fast, 512 m-blocks).
// ---------------------------------------------------------------------------
#define BM 128
#define BN 128
#define BK 32
#define STAGES 3
#define NKT (Cch / BK)          // 12
#define AROW 80                  // bytes per smem row (40 bf16)
#define ATILE (BM * AROW)        // 10240
#define WTILE (BN * AROW)        // 10240
#define GEMM_SMEM (STAGES * (ATILE + WTILE))   // 61440

__global__ __launch_bounds__(256, 2) void gemm_rope_tc(const float* __restrict__ bias)
{
    extern __shared__ __align__(16) uint8_t gsm[];
    uint8_t* smA = gsm;
    uint8_t* smW = gsm + STAGES * ATILE;

    int tid  = threadIdx.x;
    int warp = tid >> 5, lane = tid & 31;
    int wm = warp >> 2, wn = warp & 3;
    int g  = lane >> 2, l4 = lane & 3;
    int r8 = lane & 7,  qq = lane >> 3;

    int jBase = blockIdx.x * BN;
    int mBase = blockIdx.y * BM;

    const __nv_bfloat16* xblk = g_xbf + (size_t)mBase * Cch;
    const __nv_bfloat16* wblk = g_wbf + (size_t)jBase * Cch;

    int am[2], ak[2];
#pragma unroll
    for (int i = 0; i < 2; i++) { int idx = tid + i * 256; am[i] = idx >> 2; ak[i] = (idx & 3) * 8; }

    uint32_t aBase = (uint32_t)__cvta_generic_to_shared(smA);
    uint32_t wBase = (uint32_t)__cvta_generic_to_shared(smW);
    uint32_t aOff = (uint32_t)(((qq & 1) * 8 + r8) * AROW + (qq >> 1) * 16);
    uint32_t bOff = (uint32_t)(((qq >> 1) * 8 + r8) * AROW + (qq & 1) * 16);

    auto loadTile = [&](int t, int buf) {
        int k0 = t * BK;
#pragma unroll
        for (int i = 0; i < 2; i++) {
            cp16(aBase + (uint32_t)(buf * ATILE + am[i] * AROW + ak[i] * 2),
                 xblk + (size_t)am[i] * Cch + k0 + ak[i]);
            cp16(wBase + (uint32_t)(buf * WTILE + am[i] * AROW + ak[i] * 2),
                 wblk + (size_t)am[i] * Cch + k0 + ak[i]);
        }
        asm volatile("cp.async.commit_group;");
    };

    float4 c[4][4];
#pragma unroll
    for (int i = 0; i < 4; i++)
#pragma unroll
        for (int f = 0; f < 4; f++) c[i][f] = make_float4(0.f, 0.f, 0.f, 0.f);

    loadTile(0, 0);
    loadTile(1, 1);

    for (int t = 0; t < NKT; t++) {
        asm volatile("cp.async.wait_group 1;");
        __syncthreads();
        if (t + 2 < NKT) loadTile(t + 2, (t + 2) % STAGES);

        int buf = t % STAGES;
        uint32_t aT = aBase + (uint32_t)(buf * ATILE);
        uint32_t wT = wBase + (uint32_t)(buf * WTILE);
#pragma unroll
        for (int kk = 0; kk < BK; kk += 16) {
            uint32_t a[4][4], b[2][4];
#pragma unroll
            for (int mi = 0; mi < 4; mi++)
                ldm_x4(a[mi], aT + (uint32_t)((wm * 64 + mi * 16) * AROW + kk * 2) + aOff);
#pragma unroll
            for (int bg = 0; bg < 2; bg++)
                ldm_x4(b[bg], wT + (uint32_t)((wn * 32 + bg * 16) * AROW + kk * 2) + bOff);
#pragma unroll
            for (int mi = 0; mi < 4; mi++)
#pragma unroll
                for (int bg = 0; bg < 2; bg++) {
                    mma16(c[mi][bg * 2],     a[mi], b[bg][0], b[bg][1]);
                    mma16(c[mi][bg * 2 + 1], a[mi], b[bg][2], b[bg][3]);
                }
        }
    }

    // ---- fused epilogue: bias, elu+1, RoPE, k-sum; bf16 outputs ----
    bool isK = (jBase >= Cch);
    int bb = mBase >> 12;
    float ksum_loc[4][2];
#pragma unroll
    for (int f = 0; f < 4; f++) { ksum_loc[f][0] = 0.f; ksum_loc[f][1] = 0.f; }

#pragma unroll
    for (int mi = 0; mi < 4; mi++) {
        int mrow0 = mBase + wm * 64 + mi * 16 + g;
#pragma unroll
        for (int f = 0; f < 4; f++) {
            int j0 = jBase + wn * 32 + f * 8 + 2 * l4;
            int jm = isK ? (j0 - Cch) : j0;
            float b0 = bias[j0], b1 = bias[j0 + 1];
#pragma unroll
            for (int rr = 0; rr < 2; rr++) {
                int m = mrow0 + rr * 8;
                float re = (rr == 0 ? c[mi][f].x : c[mi][f].z) + b0;
                float im = (rr == 0 ? c[mi][f].y : c[mi][f].w) + b1;
                re = (re > 0.f) ? (re + 1.f) : __expf(re);
                im = (im > 0.f) ? (im + 1.f) : __expf(im);
                int n = m & (Ntok - 1);
                float2 cs = g_rope[(size_t)n * 192 + (jm >> 1)];
                float rre = cs.x * re - cs.y * im;
                float rim = cs.y * re + cs.x * im;
                size_t off = (size_t)m * Cch + jm;
                uint32_t pk = packbf(rre, rim);
                if (!isK) {
                    *(uint32_t*)&g_qrb[off] = pk;
                } else {
                    *(uint32_t*)&g_krb[off] = pk;
                    ksum_loc[f][0] += re;
                    ksum_loc[f][1] += im;
                }
            }
        }
    }

    if (isK) {
#pragma unroll
        for (int f = 0; f < 4; f++) {
#pragma unroll
            for (int e = 0; e < 2; e++) {
                float v = ksum_loc[f][e];
                v += __shfl_xor_sync(0xffffffffu, v, 4);
                v += __shfl_xor_sync(0xffffffffu, v, 8);
                v += __shfl_xor_sync(0xffffffffu, v, 16);
                if (g == 0) {
                    int jm = (jBase - Cch) + wn * 32 + f * 8 + 2 * l4 + e;
                    atomicAdd(&g_ksum[bb * Cch + jm], v);
                }
            }
        }
    }
}

// ---------------------------------------------------------------------------
// kv[b][h] += (1/N) sum_n outer(k_rope, v);  bf16 inputs, fp32 accumulate.
// ---------------------------------------------------------------------------
#define KVCH 32
#define KVSPLIT 32
#define KVROW 256
#define KVTILE (KVCH * KVROW)

__global__ __launch_bounds__(256) void kv_kernel()
{
    int b = blockIdx.x, hq = blockIdx.y, s = blockIdx.z;
    int tid = threadIdx.x;
    __shared__ __align__(16) uint8_t ksm[2 * KVTILE];
    __shared__ __align__(16) uint8_t vsm[2 * KVTILE];

    int sub = tid >> 6;
    int st  = tid & 63;
    int d0  = (st >> 3) * 4;
    int e0  = (st & 7) * 4;

    float a[4][4];
#pragma unroll
    for (int r = 0; r < 4; r++)
#pragma unroll
        for (int cc = 0; cc < 4; cc++) a[r][cc] = 0.f;

    const int CHUNK = Ntok / KVSPLIT;
    const int NSTG  = CHUNK / KVCH;
    int nBase = s * CHUNK;
    const __nv_bfloat16* kr = g_krb + ((size_t)b * Ntok + nBase) * Cch + hq * 128;
    const __nv_bfloat16* vv = g_xbf + ((size_t)b * Ntok + nBase) * Cch + hq * 128;

    int ln[2], lc[2];
#pragma unroll
    for (int i = 0; i < 2; i++) { int idx = tid + i * 256; ln[i] = idx >> 4; lc[i] = (idx & 15) * 8; }
    uint32_t ksB = (uint32_t)__cvta_generic_to_shared(ksm);
    uint32_t vsB = (uint32_t)__cvta_generic_to_shared(vsm);

    auto load_stage = [&](int stg, int buf) {
#pragma unroll
        for (int i = 0; i < 2; i++) {
            uint32_t so = (uint32_t)(buf * KVTILE + ln[i] * KVROW + lc[i] * 2);
            size_t go = (size_t)(stg * KVCH + ln[i]) * Cch + lc[i];
            cp16(ksB + so, kr + go);
            cp16(vsB + so, vv + go);
        }
        asm volatile("cp.async.commit_group;");
    };

    load_stage(0, 0);
    for (int stg = 0; stg < NSTG; stg++) {
        if (stg + 1 < NSTG) {
            load_stage(stg + 1, (stg + 1) & 1);
            asm volatile("cp.async.wait_group 1;");
        } else {
            asm volatile("cp.async.wait_group 0;");
        }
        __syncthreads();
        int buf = stg & 1;
        const uint8_t* kb = ksm + buf * KVTILE + (sub * 32 + d0) * 2;
        const uint8_t* vb = vsm + buf * KVTILE + (sub * 32 + e0) * 2;
#pragma unroll
        for (int n = 0; n < KVCH; n++) {
            const __nv_bfloat162* kp = (const __nv_bfloat162*)(kb + n * KVROW);
            const __nv_bfloat162* vp = (const __nv_bfloat162*)(vb + n * KVROW);
            float2 k01 = __bfloat1622float2(kp[0]);
            float2 k23 = __bfloat1622float2(kp[1]);
            float2 v01 = __bfloat1622float2(vp[0]);
            float2 v23 = __bfloat1622float2(vp[1]);
            float kk[4] = {k01.x, k01.y, k23.x, k23.y};
            float vr[4] = {v01.x, v01.y, v23.x, v23.y};
#pragma unroll
            for (int r = 0; r < 4; r++)
#pragma unroll
                for (int cc = 0; cc < 4; cc++) a[r][cc] += kk[r] * vr[cc];
        }
        __syncthreads();
    }

    const float inv = 1.0f / (float)Ntok;
    float* dst = g_kv + (size_t)(b * NH + hq * 4 + sub) * DH * DH;
#pragma unroll
    for (int r = 0; r < 4; r++)
#pragma unroll
        for (int cc = 0; cc < 4; cc++)
            atomicAdd(&dst[(d0 + r) * DH + e0 + cc], a[r][cc] * inv);
}

// ---------------------------------------------------------------------------
// Finalize: tensor-core attention epilogue + chunked depthwise conv (fp32 x).
// SMEM UNION (57KB) + __launch_bounds__(384,3): 3 blocks/SM.
// z-phase: chunk-4 prefetch (rope + Q) to break the serial load->reduce chain.
// ---------------------------------------------------------------------------
#define FQ_BYTES 784
#define FQ_SIZE  (32 * FQ_BYTES)            // 25088
#define FB_OFF   FQ_SIZE
#define FB_SIZE  (NH * DH * 80)             // 30720
#define FO_STRIDE 388
#define FO_SIZE  (32 * FO_STRIDE * 4)       // 49664  (< FQ_SIZE + FB_SIZE)
#define FZ_OFF   (FQ_SIZE + FB_SIZE)        // 55808
#define FIN_SMEM (FZ_OFF + NH * 32 * 4)     // 57344

__global__ __launch_bounds__(384, 3) void finalize_kernel(
    const float* __restrict__ x, const float* __restrict__ lepe_w,
    const float* __restrict__ lepe_b, float* __restrict__ out)
{
    extern __shared__ __align__(16) uint8_t fsm[];
    __nv_bfloat16* Q = (__nv_bfloat16*)fsm;
    uint8_t* Bkv = fsm + FB_OFF;
    float* O  = (float*)fsm;                 // union: valid after MMA+sync
    float* zs = (float*)(fsm + FZ_OFF);

    int hh = blockIdx.x, half = blockIdx.y, b = blockIdx.z;
    int t = threadIdx.x;
    int h = t >> 5, lane = t & 31;
    bool even = ((lane & 1) == 0);
    int n0 = hh * HRES + half * 32;

    uint32_t qB = (uint32_t)__cvta_generic_to_shared(Q);

    {
        const __nv_bfloat16* qsrc = g_qrb + ((size_t)b * Ntok + n0) * Cch;
#pragma unroll
        for (int i = 0; i < 4; i++) {
            int idx = i * 384 + t;
            int row = idx / 48, col = idx % 48;
            cp16(qB + (uint32_t)(row * FQ_BYTES + col * 16),
                 qsrc + (size_t)row * Cch + col * 8);
        }
        asm volatile("cp.async.commit_group;");
    }

    float km  = g_ksum[b * Cch + t] * (1.0f / (float)Ntok);
    float kmp = __shfl_xor_sync(0xffffffffu, km, 1);

    {
        const float* kvh = g_kv + (size_t)(b * NH + h) * DH * DH;
        __nv_bfloat16* Bh = (__nv_bfloat16*)(Bkv + h * (DH * 80));
#pragma unroll
        for (int d = 0; d < DH; d++) {
            float v = kvh[d * DH + lane];
            Bh[lane * 40 + d] = __float2bfloat16(v);
        }
    }

    asm volatile("cp.async.wait_group 0;");
    __syncthreads();

    // z-phase: chunk-4 prefetched rope + Q, interleaved reduce chains
    {
        const float2* roperow = g_rope + (size_t)n0 * 192 + (h * 16 + (lane >> 1));
#pragma unroll
        for (int wq = 0; wq < 8; wq++) {
            float2 cs4[4];
            float  qv4[4];
#pragma unroll
            for (int i = 0; i < 4; i++) {
                int w = wq * 4 + i;
                cs4[i] = roperow[(size_t)w * 192];
                qv4[i] = __bfloat162float(Q[w * 392 + h * 32 + lane]);
            }
#pragma unroll
            for (int i = 0; i < 4; i++) {
                float rkm = even ? (cs4[i].x * km - cs4[i].y * kmp)
                                 : (cs4[i].y * kmp + cs4[i].x * km);
                float prod = qv4[i] * rkm;
#pragma unroll
                for (int o = 16; o > 0; o >>= 1)
                    prod += __shfl_xor_sync(0xffffffffu, prod, o);
                if (lane == 0) zs[h * 32 + wq * 4 + i] = 1.0f / (prod + 1e-6f);
            }
        }
    }
    __syncwarp();

    float4 c[2][4];
#pragma unroll
    for (int i = 0; i < 2; i++)
#pragma unroll
        for (int f = 0; f < 4; f++) c[i][f] = make_float4(0.f, 0.f, 0.f, 0.f);
    {
        int qq = lane >> 3, r8 = lane & 7;
        uint32_t aOff = (uint32_t)(((qq & 1) * 8 + r8) * FQ_BYTES + (qq >> 1) * 16);
        uint32_t bOff = (uint32_t)(((qq >> 1) * 8 + r8) * 80 + (qq & 1) * 16);
        uint32_t bB = (uint32_t)__cvta_generic_to_shared(Bkv) + (uint32_t)(h * DH * 80);
#pragma unroll
        for (int kk = 0; kk < 32; kk += 16) {
            uint32_t a[2][4], bb[2][4];
#pragma unroll
            for (int tf = 0; tf < 2; tf++)
                ldm_x4(a[tf], qB + (uint32_t)(tf * 16 * FQ_BYTES + (h * 32 + kk) * 2) + aOff);
#pragma unroll
            for (int bg = 0; bg < 2; bg++)
                ldm_x4(bb[bg], bB + (uint32_t)(bg * 16 * 80 + kk * 2) + bOff);
#pragma unroll
            for (int tf = 0; tf < 2; tf++)
#pragma unroll
                for (int bg = 0; bg < 2; bg++) {
                    mma16(c[tf][bg * 2],     a[tf], bb[bg][0], bb[bg][1]);
                    mma16(c[tf][bg * 2 + 1], a[tf], bb[bg][2], bb[bg][3]);
                }
        }
    }

    // Phase boundary: Q/Bkv dead, O takes over the same smem.
    __syncthreads();

    {
        int g = lane >> 2, l4 = lane & 3;
#pragma unroll
        for (int tf = 0; tf < 2; tf++) {
            float zlo = zs[h * 32 + tf * 16 + g];
            float zhi = zs[h * 32 + tf * 16 + g + 8];
#pragma unroll
            for (int f = 0; f < 4; f++) {
                int e = h * 32 + f * 8 + 2 * l4;
                float* lo = &O[(tf * 16 + g) * FO_STRIDE + e];
                float* hi = &O[(tf * 16 + g + 8) * FO_STRIDE + e];
                lo[0] = c[tf][f].x * zlo;  lo[1] = c[tf][f].y * zlo;
                hi[0] = c[tf][f].z * zhi;  hi[1] = c[tf][f].w * zhi;
            }
        }
    }
    __syncthreads();

    // Phase 4: chunked depthwise 3x3 conv (fp32 x) + add O
    float wl[9];
#pragma unroll
    for (int i = 0; i < 9; i++) wl[i] = lepe_w[t * 9 + i];
    float lb = lepe_b[t];

    const size_t rowStride = (size_t)HRES * Cch;
    const float* xb = x + (size_t)b * Ntok * Cch + t;
    int wb = half * 32;
    bool rok[3];
    const float* xr[3];
#pragma unroll
    for (int r = 0; r < 3; r++) {
        int yy = hh - 1 + r;
        rok[r] = (yy >= 0 && yy < HRES);
        xr[r] = xb + (size_t)(rok[r] ? yy : 0) * rowStride;
    }

    float* orow = out + ((size_t)b * Ntok + n0) * Cch + t;

#pragma unroll
    for (int ch = 0; ch < 4; ch++) {
        int base = wb + ch * 8;
        float v[3][10];
#pragma unroll
        for (int r = 0; r < 3; r++)
#pragma unroll
            for (int j = 0; j < 10; j++) {
                int col = base - 1 + j;
                bool ok = rok[r] && col >= 0 && col < HRES;
                v[r][j] = ok ? xr[r][(size_t)col * Cch] : 0.f;
            }
#pragma unroll
        for (int w = 0; w < 8; w++) {
            float lp = lb;
#pragma unroll
            for (int r = 0; r < 3; r++)
                lp += v[r][w] * wl[r * 3 + 0] + v[r][w + 1] * wl[r * 3 + 1]
                    + v[r][w + 2] * wl[r * 3 + 2];
            int wcol = ch * 8 + w;
            orow[(size_t)wcol * Cch] = lp + O[wcol * FO_STRIDE + t];
        }
    }
}

// ---------------------------------------------------------------------------
extern "C" void kernel_launch(void* const* d_in, const int* in_sizes, int n_in,
                              void* d_out, int out_size)
{
    const float* x      = (const float*)d_in[0];
    const float* qk_w   = (const float*)d_in[1];
    const float* qk_b   = (const float*)d_in[2];
    const float* lepe_w = (const float*)d_in[3];
    const float* lepe_b = (const float*)d_in[4];
    float* out = (float*)d_out;

    static bool init = false;
    if (!init) {
        cudaFuncSetAttribute(gemm_rope_tc, cudaFuncAttributeMaxDynamicSharedMemorySize, GEMM_SMEM);
        cudaFuncSetAttribute(finalize_kernel, cudaFuncAttributeMaxDynamicSharedMemorySize, FIN_SMEM);
        init = true;
    }

    setup_kernel<<<SB_W, 256>>>(x, qk_w);
    gemm_rope_tc<<<dim3(TWOC / BN, (Bsz * Ntok) / BM), 256, GEMM_SMEM>>>(qk_b);
    kv_kernel<<<dim3(Bsz, NH / 4, KVSPLIT), 256>>>();
    finalize_kernel<<<dim3(HRES, 2, Bsz), 384, FIN_SMEM>>>(x, lepe_w, lepe_b, out);
}

// round 16
// speedup vs baseline: 1.2124x; 1.1268x over previous
#include <cuda_runtime.h>
#include <cuda_bf16.h>
#include <cstdint>

#define Bsz 16
#define Ntok 4096
#define Cch 384
#define HRES 64
#define NH 12
#define DH 32
#define TWOC 768

// Scratch (device globals: allocation-free rule)
__device__ __nv_bfloat16 g_xbf[Bsz * Ntok * Cch];   // bf16 copy of x
__device__ __nv_bfloat16 g_wbf[TWOC * Cch];         // bf16 copy of qk_w
__device__ __nv_bfloat16 g_qrb[Bsz * Ntok * Cch];   // roped q (bf16)
__device__ __nv_bfloat16 g_krb[Bsz * Ntok * Cch];   // roped k (bf16)
__device__ float  g_ksum[Bsz * Cch];                // sum_n k (unroped, fp32)
__device__ float  g_kv  [Bsz * NH * DH * DH];
__device__ float2 g_rope[Ntok * (Cch / 2)];

// ---------------------------------------------------------------------------
__device__ __forceinline__ uint32_t packbf(float a, float b) {
    __nv_bfloat162 h = __float22bfloat162_rn(make_float2(a, b));
    return *reinterpret_cast<uint32_t*>(&h);
}

__device__ __forceinline__ void ldm_x4(uint32_t* d, uint32_t addr) {
    asm volatile("ldmatrix.sync.aligned.m8n8.x4.shared.b16 {%0,%1,%2,%3}, [%4];"
                 : "=r"(d[0]), "=r"(d[1]), "=r"(d[2]), "=r"(d[3]) : "r"(addr));
}

__device__ __forceinline__ void ldm_x4t(uint32_t* d, uint32_t addr) {
    asm volatile("ldmatrix.sync.aligned.m8n8.x4.trans.shared.b16 {%0,%1,%2,%3}, [%4];"
                 : "=r"(d[0]), "=r"(d[1]), "=r"(d[2]), "=r"(d[3]) : "r"(addr));
}

__device__ __forceinline__ void mma16(float4& d, const uint32_t* a,
                                      uint32_t b0, uint32_t b1) {
    asm volatile(
        "mma.sync.aligned.m16n8k16.row.col.f32.bf16.bf16.f32 "
        "{%0,%1,%2,%3},{%4,%5,%6,%7},{%8,%9},{%0,%1,%2,%3};\n"
        : "+f"(d.x), "+f"(d.y), "+f"(d.z), "+f"(d.w)
        : "r"(a[0]), "r"(a[1]), "r"(a[2]), "r"(a[3]), "r"(b0), "r"(b1));
}

__device__ __forceinline__ void cp16(uint32_t smem, const void* g) {
    asm volatile("cp.async.cg.shared.global [%0], [%1], 16;" :: "r"(smem), "l"(g));
}

// ---------------------------------------------------------------------------
// Fused setup: rope table + zero scratch + bf16 conversion, one launch.
// ---------------------------------------------------------------------------
#define SB_ROPE 3072
#define SB_ZERO (SB_ROPE + 768)
#define SB_X    (SB_ZERO + 12288)
#define SB_W    (SB_X + 144)

__global__ __launch_bounds__(256) void setup_kernel(
    const float* __restrict__ x, const float* __restrict__ w)
{
    int blk = blockIdx.x;
    if (blk < SB_ROPE) {
        int i = blk * 256 + threadIdx.x;      // < 786432
        int n = i / 192, p = i % 192;
        int hh = n >> 6, ww = n & 63;
        int j = (p < 96) ? p : (p - 96);
        float theta = __expf(-((float)j * (1.0f / 96.0f)) * 9.210340371976184f);
        float pos = (p < 96) ? (float)hh : (float)ww;
        float s, c;
        sincosf(pos * theta, &s, &c);
        g_rope[(size_t)n * 192 + p] = make_float2(c, s);
    } else if (blk < SB_ZERO) {
        int i = (blk - SB_ROPE) * 256 + threadIdx.x;   // < 196608
        if (i < Bsz * Cch) g_ksum[i] = 0.f;
        g_kv[i] = 0.f;
    } else if (blk < SB_X) {
        size_t o = ((size_t)(blk - SB_ZERO) * 256 + threadIdx.x) * 8;
        float4 a = *(const float4*)(x + o);
        float4 b = *(const float4*)(x + o + 4);
        uint4 u = make_uint4(packbf(a.x, a.y), packbf(a.z, a.w),
                             packbf(b.x, b.y), packbf(b.z, b.w));
        *(uint4*)&g_xbf[o] = u;
    } else {
        size_t o = ((size_t)(blk - SB_X) * 256 + threadIdx.x) * 8;
        if (o < (size_t)TWOC * Cch) {
            float4 a = *(const float4*)(w + o);
            float4 b = *(const float4*)(w + o + 4);
            uint4 u = make_uint4(packbf(a.x, a.y), packbf(a.z, a.w),
                                 packbf(b.x, b.y), packbf(b.z, b.w));
            *(uint4*)&g_wbf[o] = u;
        }
    }
}

// ---------------------------------------------------------------------------
// GEMM qk = x @ W^T + b via bf16 MMA, cp.async 3-stage pipeline (R11 proven).
// BM=128 BN=128 BK=32, 256 threads (8 warps: 2 in M x 4 in N), warp 64x32.
// ---------------------------------------------------------------------------
#define BM 128
#define BN 128
#define BK 32
#define STAGES 3
#define NKT (Cch / BK)          // 12
#define AROW 80                  // bytes per smem row (40 bf16)
#define ATILE (BM * AROW)        // 10240
#define WTILE (BN * AROW)        // 10240
#define GEMM_SMEM (STAGES * (ATILE + WTILE))   // 61440

__global__ __launch_bounds__(256, 2) void gemm_rope_tc(const float* __restrict__ bias)
{
    extern __shared__ __align__(16) uint8_t gsm[];
    uint8_t* smA = gsm;
    uint8_t* smW = gsm + STAGES * ATILE;

    int tid  = threadIdx.x;
    int warp = tid >> 5, lane = tid & 31;
    int wm = warp >> 2, wn = warp & 3;
    int g  = lane >> 2, l4 = lane & 3;
    int r8 = lane & 7,  qq = lane >> 3;

    int jBase = blockIdx.x * BN;
    int mBase = blockIdx.y * BM;

    const __nv_bfloat16* xblk = g_xbf + (size_t)mBase * Cch;
    const __nv_bfloat16* wblk = g_wbf + (size_t)jBase * Cch;

    int am[2], ak[2];
#pragma unroll
    for (int i = 0; i < 2; i++) { int idx = tid + i * 256; am[i] = idx >> 2; ak[i] = (idx & 3) * 8; }

    uint32_t aBase = (uint32_t)__cvta_generic_to_shared(smA);
    uint32_t wBase = (uint32_t)__cvta_generic_to_shared(smW);
    uint32_t aOff = (uint32_t)(((qq & 1) * 8 + r8) * AROW + (qq >> 1) * 16);
    uint32_t bOff = (uint32_t)(((qq >> 1) * 8 + r8) * AROW + (qq & 1) * 16);

    auto loadTile = [&](int t, int buf) {
        int k0 = t * BK;
#pragma unroll
        for (int i = 0; i < 2; i++) {
            cp16(aBase + (uint32_t)(buf * ATILE + am[i] * AROW + ak[i] * 2),
                 xblk + (size_t)am[i] * Cch + k0 + ak[i]);
            cp16(wBase + (uint32_t)(buf * WTILE + am[i] * AROW + ak[i] * 2),
                 wblk + (size_t)am[i] * Cch + k0 + ak[i]);
        }
        asm volatile("cp.async.commit_group;");
    };

    float4 c[4][4];
#pragma unroll
    for (int i = 0; i < 4; i++)
#pragma unroll
        for (int f = 0; f < 4; f++) c[i][f] = make_float4(0.f, 0.f, 0.f, 0.f);

    loadTile(0, 0);
    loadTile(1, 1);

    for (int t = 0; t < NKT; t++) {
        asm volatile("cp.async.wait_group 1;");
        __syncthreads();
        if (t + 2 < NKT) loadTile(t + 2, (t + 2) % STAGES);

        int buf = t % STAGES;
        uint32_t aT = aBase + (uint32_t)(buf * ATILE);
        uint32_t wT = wBase + (uint32_t)(buf * WTILE);
#pragma unroll
        for (int kk = 0; kk < BK; kk += 16) {
            uint32_t a[4][4], b[2][4];
#pragma unroll
            for (int mi = 0; mi < 4; mi++)
                ldm_x4(a[mi], aT + (uint32_t)((wm * 64 + mi * 16) * AROW + kk * 2) + aOff);
#pragma unroll
            for (int bg = 0; bg < 2; bg++)
                ldm_x4(b[bg], wT + (uint32_t)((wn * 32 + bg * 16) * AROW + kk * 2) + bOff);
#pragma unroll
            for (int mi = 0; mi < 4; mi++)
#pragma unroll
                for (int bg = 0; bg < 2; bg++) {
                    mma16(c[mi][bg * 2],     a[mi], b[bg][0], b[bg][1]);
                    mma16(c[mi][bg * 2 + 1], a[mi], b[bg][2], b[bg][3]);
                }
        }
    }

    // ---- fused epilogue: bias, elu+1, RoPE, k-sum; bf16 outputs ----
    bool isK = (jBase >= Cch);
    int bb = mBase >> 12;
    float ksum_loc[4][2];
#pragma unroll
    for (int f = 0; f < 4; f++) { ksum_loc[f][0] = 0.f; ksum_loc[f][1] = 0.f; }

#pragma unroll
    for (int mi = 0; mi < 4; mi++) {
        int mrow0 = mBase + wm * 64 + mi * 16 + g;
#pragma unroll
        for (int f = 0; f < 4; f++) {
            int j0 = jBase + wn * 32 + f * 8 + 2 * l4;
            int jm = isK ? (j0 - Cch) : j0;
            float b0 = bias[j0], b1 = bias[j0 + 1];
#pragma unroll
            for (int rr = 0; rr < 2; rr++) {
                int m = mrow0 + rr * 8;
                float re = (rr == 0 ? c[mi][f].x : c[mi][f].z) + b0;
                float im = (rr == 0 ? c[mi][f].y : c[mi][f].w) + b1;
                re = (re > 0.f) ? (re + 1.f) : __expf(re);
                im = (im > 0.f) ? (im + 1.f) : __expf(im);
                int n = m & (Ntok - 1);
                float2 cs = g_rope[(size_t)n * 192 + (jm >> 1)];
                float rre = cs.x * re - cs.y * im;
                float rim = cs.y * re + cs.x * im;
                size_t off = (size_t)m * Cch + jm;
                uint32_t pk = packbf(rre, rim);
                if (!isK) {
                    *(uint32_t*)&g_qrb[off] = pk;
                } else {
                    *(uint32_t*)&g_krb[off] = pk;
                    ksum_loc[f][0] += re;
                    ksum_loc[f][1] += im;
                }
            }
        }
    }

    if (isK) {
#pragma unroll
        for (int f = 0; f < 4; f++) {
#pragma unroll
            for (int e = 0; e < 2; e++) {
                float v = ksum_loc[f][e];
                v += __shfl_xor_sync(0xffffffffu, v, 4);
                v += __shfl_xor_sync(0xffffffffu, v, 8);
                v += __shfl_xor_sync(0xffffffffu, v, 16);
                if (g == 0) {
                    int jm = (jBase - Cch) + wn * 32 + f * 8 + 2 * l4 + e;
                    atomicAdd(&g_ksum[bb * Cch + jm], v);
                }
            }
        }
    }
}

// ---------------------------------------------------------------------------
// kv[b][h] = (1/N) k_rope^T @ v via bf16 MMA (ldmatrix.trans both operands).
// grid (16, 12, 8): one head x 512 tokens per block, 256 threads (8 warps).
// Warp w covers tokens [w*64, w*64+64): 4 k16-steps x 8 mma.
// 8 warp-partials reduced via padded smem, then 4 atomicAdds/thread.
// ---------------------------------------------------------------------------
#define KVTOK 512
#define KVSPL (Ntok / KVTOK)     // 8
#define KRS 80                    // padded row bytes (40 bf16, 32 used)
#define KARR (KVTOK * KRS)        // 40960
#define KV_SMEM (2 * KARR)        // 81920
#define DPS 36                    // Dp row stride (floats), conflict-free

__global__ __launch_bounds__(256, 2) void kv_kernel()
{
    extern __shared__ __align__(16) uint8_t kvsm[];
    int b = blockIdx.x, h = blockIdx.y, s = blockIdx.z;
    int tid = threadIdx.x;
    int warp = tid >> 5, lane = tid & 31;
    int g = lane >> 2, l4 = lane & 3;
    int q = lane >> 3, r8 = lane & 7;

    uint32_t kB = (uint32_t)__cvta_generic_to_shared(kvsm);
    uint32_t vB = kB + KARR;

    int nBase = s * KVTOK;
    const __nv_bfloat16* kr = g_krb + ((size_t)b * Ntok + nBase) * Cch + h * DH;
    const __nv_bfloat16* vv = g_xbf + ((size_t)b * Ntok + nBase) * Cch + h * DH;

    // load 512 rows x 64B (4 x 16B chunks) per array: 8 chunks/thread/array
#pragma unroll
    for (int i = 0; i < 8; i++) {
        int idx = tid + i * 256;            // 0..2047
        int row = idx >> 2, ch = idx & 3;
        uint32_t so = (uint32_t)(row * KRS + ch * 16);
        size_t go = (size_t)row * Cch + ch * 8;
        cp16(kB + so, kr + go);
        cp16(vB + so, vv + go);
    }
    asm volatile("cp.async.commit_group;");
    asm volatile("cp.async.wait_group 0;");
    __syncthreads();

    // trans ldsm offsets (derived by mirroring the working GEMM maps):
    // A (k_rope -> [d][tok]):  row = token (q>>1)*8+r8, col = d half (q&1)*16
    uint32_t aOffT = (uint32_t)(((q >> 1) * 8 + r8) * KRS + (q & 1) * 16);
    // B (v -> [e][tok]):       row = token (q&1)*8+r8,  col = e half (q>>1)*16
    uint32_t bOffT = (uint32_t)(((q & 1) * 8 + r8) * KRS + (q >> 1) * 16);

    float4 c[2][4];
#pragma unroll
    for (int i = 0; i < 2; i++)
#pragma unroll
        for (int f = 0; f < 4; f++) c[i][f] = make_float4(0.f, 0.f, 0.f, 0.f);

    int tok0 = warp * 64;
#pragma unroll
    for (int ks = 0; ks < 4; ks++) {
        uint32_t tb = (uint32_t)((tok0 + ks * 16) * KRS);
        uint32_t a[2][4], bb[2][4];
#pragma unroll
        for (int mi = 0; mi < 2; mi++)
            ldm_x4t(a[mi], kB + tb + (uint32_t)(mi * 32) + aOffT);
#pragma unroll
        for (int eb = 0; eb < 2; eb++)
            ldm_x4t(bb[eb], vB + tb + (uint32_t)(eb * 32) + bOffT);
#pragma unroll
        for (int mi = 0; mi < 2; mi++)
#pragma unroll
            for (int eb = 0; eb < 2; eb++) {
                mma16(c[mi][eb * 2],     a[mi], bb[eb][0], bb[eb][1]);
                mma16(c[mi][eb * 2 + 1], a[mi], bb[eb][2], bb[eb][3]);
            }
    }

    // cross-warp reduction through padded smem (k/v tiles dead)
    __syncthreads();
    float* Dp = (float*)kvsm;               // 8 * 32 * DPS * 4 = 36864 <= KV_SMEM
#pragma unroll
    for (int mi = 0; mi < 2; mi++)
#pragma unroll
        for (int f = 0; f < 4; f++) {
            int d = mi * 16 + g;
            int e = f * 8 + 2 * l4;
            float* lo = &Dp[warp * (32 * DPS) + d * DPS + e];
            float* hi = &Dp[warp * (32 * DPS) + (d + 8) * DPS + e];
            lo[0] = c[mi][f].x;  lo[1] = c[mi][f].y;
            hi[0] = c[mi][f].z;  hi[1] = c[mi][f].w;
        }
    __syncthreads();

    // each thread sums 4 consecutive e for one d across 8 warps
    int d = tid >> 3, e = (tid & 7) * 4;
    float4 sum = make_float4(0.f, 0.f, 0.f, 0.f);
#pragma unroll
    for (int w = 0; w < 8; w++) {
        float4 p = *(float4*)&Dp[w * (32 * DPS) + d * DPS + e];
        sum.x += p.x; sum.y += p.y; sum.z += p.z; sum.w += p.w;
    }
    const float inv = 1.0f / (float)Ntok;
    float* dst = g_kv + (size_t)(b * NH + h) * DH * DH + d * DH + e;
    atomicAdd(dst + 0, sum.x * inv);
    atomicAdd(dst + 1, sum.y * inv);
    atomicAdd(dst + 2, sum.z * inv);
    atomicAdd(dst + 3, sum.w * inv);
}

// ---------------------------------------------------------------------------
// Finalize: tensor-core attention epilogue + chunked depthwise conv (fp32 x).
// SMEM UNION (57KB) + __launch_bounds__(384,3): 3 blocks/SM.
// z-phase: chunk-4 prefetch (rope + Q) to break the serial load->reduce chain.
// ---------------------------------------------------------------------------
#define FQ_BYTES 784
#define FQ_SIZE  (32 * FQ_BYTES)            // 25088
#define FB_OFF   FQ_SIZE
#define FB_SIZE  (NH * DH * 80)             // 30720
#define FO_STRIDE 388
#define FO_SIZE  (32 * FO_STRIDE * 4)       // 49664  (< FQ_SIZE + FB_SIZE)
#define FZ_OFF   (FQ_SIZE + FB_SIZE)        // 55808
#define FIN_SMEM (FZ_OFF + NH * 32 * 4)     // 57344

__global__ __launch_bounds__(384, 3) void finalize_kernel(
    const float* __restrict__ x, const float* __restrict__ lepe_w,
    const float* __restrict__ lepe_b, float* __restrict__ out)
{
    extern __shared__ __align__(16) uint8_t fsm[];
    __nv_bfloat16* Q = (__nv_bfloat16*)fsm;
    uint8_t* Bkv = fsm + FB_OFF;
    float* O  = (float*)fsm;                 // union: valid after MMA+sync
    float* zs = (float*)(fsm + FZ_OFF);

    int hh = blockIdx.x, half = blockIdx.y, b = blockIdx.z;
    int t = threadIdx.x;
    int h = t >> 5, lane = t & 31;
    bool even = ((lane & 1) == 0);
    int n0 = hh * HRES + half * 32;

    uint32_t qB = (uint32_t)__cvta_generic_to_shared(Q);

    {
        const __nv_bfloat16* qsrc = g_qrb + ((size_t)b * Ntok + n0) * Cch;
#pragma unroll
        for (int i = 0; i < 4; i++) {
            int idx = i * 384 + t;
            int row = idx / 48, col = idx % 48;
            cp16(qB + (uint32_t)(row * FQ_BYTES + col * 16),
                 qsrc + (size_t)row * Cch + col * 8);
        }
        asm volatile("cp.async.commit_group;");
    }

    float km  = g_ksum[b * Cch + t] * (1.0f / (float)Ntok);
    float kmp = __shfl_xor_sync(0xffffffffu, km, 1);

    {
        const float* kvh = g_kv + (size_t)(b * NH + h) * DH * DH;
        __nv_bfloat16* Bh = (__nv_bfloat16*)(Bkv + h * (DH * 80));
#pragma unroll
        for (int d = 0; d < DH; d++) {
            float v = kvh[d * DH + lane];
            Bh[lane * 40 + d] = __float2bfloat16(v);
        }
    }

    asm volatile("cp.async.wait_group 0;");
    __syncthreads();

    // z-phase: chunk-4 prefetched rope + Q, interleaved reduce chains
    {
        const float2* roperow = g_rope + (size_t)n0 * 192 + (h * 16 + (lane >> 1));
#pragma unroll
        for (int wq = 0; wq < 8; wq++) {
            float2 cs4[4];
            float  qv4[4];
#pragma unroll
            for (int i = 0; i < 4; i++) {
                int w = wq * 4 + i;
                cs4[i] = roperow[(size_t)w * 192];
                qv4[i] = __bfloat162float(Q[w * 392 + h * 32 + lane]);
            }
#pragma unroll
            for (int i = 0; i < 4; i++) {
                float rkm = even ? (cs4[i].x * km - cs4[i].y * kmp)
                                 : (cs4[i].y * kmp + cs4[i].x * km);
                float prod = qv4[i] * rkm;
#pragma unroll
                for (int o = 16; o > 0; o >>= 1)
                    prod += __shfl_xor_sync(0xffffffffu, prod, o);
                if (lane == 0) zs[h * 32 + wq * 4 + i] = 1.0f / (prod + 1e-6f);
            }
        }
    }
    __syncwarp();

    float4 c[2][4];
#pragma unroll
    for (int i = 0; i < 2; i++)
#pragma unroll
        for (int f = 0; f < 4; f++) c[i][f] = make_float4(0.f, 0.f, 0.f, 0.f);
    {
        int qq = lane >> 3, r8 = lane & 7;
        uint32_t aOff = (uint32_t)(((qq & 1) * 8 + r8) * FQ_BYTES + (qq >> 1) * 16);
        uint32_t bOff = (uint32_t)(((qq >> 1) * 8 + r8) * 80 + (qq & 1) * 16);
        uint32_t bB = (uint32_t)__cvta_generic_to_shared(Bkv) + (uint32_t)(h * DH * 80);
#pragma unroll
        for (int kk = 0; kk < 32; kk += 16) {
            uint32_t a[2][4], bb[2][4];
#pragma unroll
            for (int tf = 0; tf < 2; tf++)
                ldm_x4(a[tf], qB + (uint32_t)(tf * 16 * FQ_BYTES + (h * 32 + kk) * 2) + aOff);
#pragma unroll
            for (int bg = 0; bg < 2; bg++)
                ldm_x4(bb[bg], bB + (uint32_t)(bg * 16 * 80 + kk * 2) + bOff);
#pragma unroll
            for (int tf = 0; tf < 2; tf++)
#pragma unroll
                for (int bg = 0; bg < 2; bg++) {
                    mma16(c[tf][bg * 2],     a[tf], bb[bg][0], bb[bg][1]);
                    mma16(c[tf][bg * 2 + 1], a[tf], bb[bg][2], bb[bg][3]);
                }
        }
    }

    // Phase boundary: Q/Bkv dead, O takes over the same smem.
    __syncthreads();

    {
        int g = lane >> 2, l4 = lane & 3;
#pragma unroll
        for (int tf = 0; tf < 2; tf++) {
            float zlo = zs[h * 32 + tf * 16 + g];
            float zhi = zs[h * 32 + tf * 16 + g + 8];
#pragma unroll
            for (int f = 0; f < 4; f++) {
                int e = h * 32 + f * 8 + 2 * l4;
                float* lo = &O[(tf * 16 + g) * FO_STRIDE + e];
                float* hi = &O[(tf * 16 + g + 8) * FO_STRIDE + e];
                lo[0] = c[tf][f].x * zlo;  lo[1] = c[tf][f].y * zlo;
                hi[0] = c[tf][f].z * zhi;  hi[1] = c[tf][f].w * zhi;
            }
        }
    }
    __syncthreads();

    // Phase 4: chunked depthwise 3x3 conv (fp32 x) + add O
    float wl[9];
#pragma unroll
    for (int i = 0; i < 9; i++) wl[i] = lepe_w[t * 9 + i];
    float lb = lepe_b[t];

    const size_t rowStride = (size_t)HRES * Cch;
    const float* xb = x + (size_t)b * Ntok * Cch + t;
    int wb = half * 32;
    bool rok[3];
    const float* xr[3];
#pragma unroll
    for (int r = 0; r < 3; r++) {
        int yy = hh - 1 + r;
        rok[r] = (yy >= 0 && yy < HRES);
        xr[r] = xb + (size_t)(rok[r] ? yy : 0) * rowStride;
    }

    float* orow = out + ((size_t)b * Ntok + n0) * Cch + t;

#pragma unroll
    for (int ch = 0; ch < 4; ch++) {
        int base = wb + ch * 8;
        float v[3][10];
#pragma unroll
        for (int r = 0; r < 3; r++)
#pragma unroll
            for (int j = 0; j < 10; j++) {
                int col = base - 1 + j;
                bool ok = rok[r] && col >= 0 && col < HRES;
                v[r][j] = ok ? xr[r][(size_t)col * Cch] : 0.f;
            }
#pragma unroll
        for (int w = 0; w < 8; w++) {
            float lp = lb;
#pragma unroll
            for (int r = 0; r < 3; r++)
                lp += v[r][w] * wl[r * 3 + 0] + v[r][w + 1] * wl[r * 3 + 1]
                    + v[r][w + 2] * wl[r * 3 + 2];
            int wcol = ch * 8 + w;
            orow[(size_t)wcol * Cch] = lp + O[wcol * FO_STRIDE + t];
        }
    }
}

// ---------------------------------------------------------------------------
extern "C" void kernel_launch(void* const* d_in, const int* in_sizes, int n_in,
                              void* d_out, int out_size)
{
    const float* x      = (const float*)d_in[0];
    const float* qk_w   = (const float*)d_in[1];
    const float* qk_b   = (const float*)d_in[2];
    const float* lepe_w = (const float*)d_in[3];
    const float* lepe_b = (const float*)d_in[4];
    float* out = (float*)d_out;

    static bool init = false;
    if (!init) {
        cudaFuncSetAttribute(gemm_rope_tc, cudaFuncAttributeMaxDynamicSharedMemorySize, GEMM_SMEM);
        cudaFuncSetAttribute(kv_kernel, cudaFuncAttributeMaxDynamicSharedMemorySize, KV_SMEM);
        cudaFuncSetAttribute(finalize_kernel, cudaFuncAttributeMaxDynamicSharedMemorySize, FIN_SMEM);
        init = true;
    }

    setup_kernel<<<SB_W, 256>>>(x, qk_w);
    gemm_rope_tc<<<dim3(TWOC / BN, (Bsz * Ntok) / BM), 256, GEMM_SMEM>>>(qk_b);
    kv_kernel<<<dim3(Bsz, NH, KVSPL), 256, KV_SMEM>>>();
    finalize_kernel<<<dim3(HRES, 2, Bsz), 384, FIN_SMEM>>>(x, lepe_w, lepe_b, out);
}

// round 17
// speedup vs baseline: 1.2209x; 1.0070x over previous
#include <cuda_runtime.h>
#include <cuda_bf16.h>
#include <cstdint>

#define Bsz 16
#define Ntok 4096
#define Cch 384
#define HRES 64
#define NH 12
#define DH 32
#define TWOC 768

// Scratch (device globals: allocation-free rule)
__device__ __nv_bfloat16 g_xbf[Bsz * Ntok * Cch];   // bf16 x, row-major (kv)
__device__ __nv_bfloat16 g_xbt[Bsz * Ntok * Cch];   // bf16 x, 8KB tiles swizzled (GEMM A)
__device__ __nv_bfloat16 g_wbt[TWOC * Cch];         // bf16 w, 8KB tiles swizzled (GEMM B)
__device__ __nv_bfloat16 g_qrb[Bsz * Ntok * Cch];   // roped q (bf16)
__device__ __nv_bfloat16 g_krb[Bsz * Ntok * Cch];   // roped k (bf16)
__device__ float  g_ksum[Bsz * Cch];                // sum_n k (unroped, fp32)
__device__ float  g_kv  [Bsz * NH * DH * DH];
__device__ float2 g_rope[Ntok * (Cch / 2)];

// ---------------------------------------------------------------------------
__device__ __forceinline__ uint32_t packbf(float a, float b) {
    __nv_bfloat162 h = __float22bfloat162_rn(make_float2(a, b));
    return *reinterpret_cast<uint32_t*>(&h);
}

__device__ __forceinline__ void ldm_x4(uint32_t* d, uint32_t addr) {
    asm volatile("ldmatrix.sync.aligned.m8n8.x4.shared.b16 {%0,%1,%2,%3}, [%4];"
                 : "=r"(d[0]), "=r"(d[1]), "=r"(d[2]), "=r"(d[3]) : "r"(addr));
}

__device__ __forceinline__ void ldm_x4t(uint32_t* d, uint32_t addr) {
    asm volatile("ldmatrix.sync.aligned.m8n8.x4.trans.shared.b16 {%0,%1,%2,%3}, [%4];"
                 : "=r"(d[0]), "=r"(d[1]), "=r"(d[2]), "=r"(d[3]) : "r"(addr));
}

__device__ __forceinline__ void mma16(float4& d, const uint32_t* a,
                                      uint32_t b0, uint32_t b1) {
    asm volatile(
        "mma.sync.aligned.m16n8k16.row.col.f32.bf16.bf16.f32 "
        "{%0,%1,%2,%3},{%4,%5,%6,%7},{%8,%9},{%0,%1,%2,%3};\n"
        : "+f"(d.x), "+f"(d.y), "+f"(d.z), "+f"(d.w)
        : "r"(a[0]), "r"(a[1]), "r"(a[2]), "r"(a[3]), "r"(b0), "r"(b1));
}

__device__ __forceinline__ void cp16(uint32_t smem, const void* g) {
    asm volatile("cp.async.cg.shared.global [%0], [%1], 16;" :: "r"(smem), "l"(g));
}

__device__ __forceinline__ void mbar_init(uint32_t a, uint32_t cnt) {
    asm volatile("mbarrier.init.shared.b64 [%0], %1;" :: "r"(a), "r"(cnt) : "memory");
}
__device__ __forceinline__ void mbar_expect(uint32_t a, uint32_t bytes) {
    asm volatile("mbarrier.arrive.expect_tx.shared.b64 _, [%0], %1;"
                 :: "r"(a), "r"(bytes) : "memory");
}
__device__ __forceinline__ void bulkcp(uint32_t dst, const void* src,
                                       uint32_t bytes, uint32_t mbar) {
    asm volatile(
        "cp.async.bulk.shared::cluster.global.mbarrier::complete_tx::bytes "
        "[%0], [%1], %2, [%3];"
        :: "r"(dst), "l"(src), "r"(bytes), "r"(mbar) : "memory");
}
__device__ __forceinline__ void mbar_wait(uint32_t a, uint32_t parity) {
    asm volatile(
        "{\n\t.reg .pred P;\n\tWAITL_%=:\n\t"
        "mbarrier.try_wait.parity.shared.b64 P, [%0], %1;\n\t"
        "@!P bra WAITL_%=;\n\t}"
        :: "r"(a), "r"(parity) : "memory");
}

// ---------------------------------------------------------------------------
// Fused setup: rope + zero + bf16 conversions (row-major x; tiled x; tiled w).
// Tiled layout: tile (rowblk, ktile) = 8KB of 128 rows x 64B; within a row,
// 16B chunk c stored at c' = c ^ ((row>>1)&3)  (ldmatrix conflict-free).
// ---------------------------------------------------------------------------
#define SB_ROPE 3072
#define SB_ZERO (SB_ROPE + 768)
#define SB_X    (SB_ZERO + 12288)
#define SB_W    (SB_X + 144)

__global__ __launch_bounds__(256) void setup_kernel(
    const float* __restrict__ x, const float* __restrict__ w)
{
    int blk = blockIdx.x;
    if (blk < SB_ROPE) {
        int i = blk * 256 + threadIdx.x;      // < 786432
        int n = i / 192, p = i % 192;
        int hh = n >> 6, ww = n & 63;
        int j = (p < 96) ? p : (p - 96);
        float theta = __expf(-((float)j * (1.0f / 96.0f)) * 9.210340371976184f);
        float pos = (p < 96) ? (float)hh : (float)ww;
        float s, c;
        sincosf(pos * theta, &s, &c);
        g_rope[(size_t)n * 192 + p] = make_float2(c, s);
    } else if (blk < SB_ZERO) {
        int i = (blk - SB_ROPE) * 256 + threadIdx.x;   // < 196608
        if (i < Bsz * Cch) g_ksum[i] = 0.f;
        g_kv[i] = 0.f;
    } else if (blk < SB_X) {
        size_t o = ((size_t)(blk - SB_ZERO) * 256 + threadIdx.x) * 8;
        float4 a = *(const float4*)(x + o);
        float4 b = *(const float4*)(x + o + 4);
        uint4 u = make_uint4(packbf(a.x, a.y), packbf(a.z, a.w),
                             packbf(b.x, b.y), packbf(b.z, b.w));
        *(uint4*)&g_xbf[o] = u;                         // row-major copy
        int m = (int)(o / Cch), k = (int)(o % Cch);     // tiled + swizzled copy
        int tile = (m >> 7) * 12 + (k >> 5);
        int r = m & 127, c = (k >> 3) & 3;
        int cs = c ^ ((r >> 1) & 3);
        *(uint4*)&g_xbt[(size_t)tile * 4096 + r * 32 + cs * 8] = u;
    } else {
        size_t o = ((size_t)(blk - SB_X) * 256 + threadIdx.x) * 8;
        if (o < (size_t)TWOC * Cch) {
            float4 a = *(const float4*)(w + o);
            float4 b = *(const float4*)(w + o + 4);
            uint4 u = make_uint4(packbf(a.x, a.y), packbf(a.z, a.w),
                                 packbf(b.x, b.y), packbf(b.z, b.w));
            int j = (int)(o / Cch), k = (int)(o % Cch);
            int tile = (j >> 7) * 12 + (k >> 5);
            int r = j & 127, c = (k >> 3) & 3;
            int cs = c ^ ((r >> 1) & 3);
            *(uint4*)&g_wbt[(size_t)tile * 4096 + r * 32 + cs * 8] = u;
        }
    }
}

// ---------------------------------------------------------------------------
// GEMM qk = x @ W^T + b via bf16 MMA, cp.async.bulk 3-stage mbarrier pipeline.
// BM=128 BN=128 BK=32, 256 threads (8 warps: 2M x 4N), warp 64x32.
// One 8KB bulk copy per operand per K-tile (2 instrs vs 1024 LDGSTS).
// ---------------------------------------------------------------------------
#define BM 128
#define BN 128
#define BK 32
#define NKT (Cch / BK)            // 12
#define TILEB 8192
#define GEMM_SMEM (6 * TILEB)     // 49152: 3 A stages + 3 W stages

__global__ __launch_bounds__(256, 2) void gemm_rope_tc(const float* __restrict__ bias)
{
    extern __shared__ __align__(16) uint8_t gsm[];
    __shared__ __align__(8) uint64_t mbars[3];

    int tid  = threadIdx.x;
    int warp = tid >> 5, lane = tid & 31;
    int wm = warp >> 2, wn = warp & 3;
    int g  = lane >> 2, l4 = lane & 3;
    int r8 = lane & 7,  qq = lane >> 3;

    int jblk = blockIdx.x, mblk = blockIdx.y;
    int jBase = jblk * BN;
    int mBase = mblk * BM;

    uint32_t aBase = (uint32_t)__cvta_generic_to_shared(gsm);
    uint32_t wBase = aBase + 3 * TILEB;
    uint32_t mbB = (uint32_t)__cvta_generic_to_shared(mbars);

    if (tid == 0) {
#pragma unroll
        for (int s = 0; s < 3; s++) mbar_init(mbB + s * 8, 1u);
    }
    __syncthreads();

    const uint8_t* gA = (const uint8_t*)g_xbt + (size_t)mblk * 12 * TILEB;
    const uint8_t* gW = (const uint8_t*)g_wbt + (size_t)jblk * 12 * TILEB;

    auto loadT = [&](int t) {
        if (tid == 0) {
            int s = t % 3;
            uint32_t mb = mbB + s * 8;
            mbar_expect(mb, 2 * TILEB);
            bulkcp(aBase + s * TILEB, gA + (size_t)t * TILEB, TILEB, mb);
            bulkcp(wBase + s * TILEB, gW + (size_t)t * TILEB, TILEB, mb);
        }
    };

    // per-lane swizzled ldsm offsets (row-local part; tile-row base mult of 16)
    int rlA = (qq & 1) * 8 + r8;           // A fragment row-local
    int rlW = (qq >> 1) * 8 + r8;          // B fragment row-local
    int swA = (rlA >> 1) & 3, swW = (rlW >> 1) & 3;

    float4 c[4][4];
#pragma unroll
    for (int i = 0; i < 4; i++)
#pragma unroll
        for (int f = 0; f < 4; f++) c[i][f] = make_float4(0.f, 0.f, 0.f, 0.f);

    loadT(0);
    loadT(1);

    for (int t = 0; t < NKT; t++) {
        mbar_wait(mbB + (t % 3) * 8, (uint32_t)((t / 3) & 1));
        __syncthreads();
        if (t + 2 < NKT) loadT(t + 2);

        uint32_t aT = aBase + (uint32_t)((t % 3) * TILEB);
        uint32_t wT = wBase + (uint32_t)((t % 3) * TILEB);
#pragma unroll
        for (int kk = 0; kk < BK; kk += 16) {
            int cA = (kk >> 3) + (qq >> 1);
            int cW = (kk >> 3) + (qq & 1);
            uint32_t a[4][4], b[2][4];
#pragma unroll
            for (int mi = 0; mi < 4; mi++)
                ldm_x4(a[mi], aT + (uint32_t)((wm * 64 + mi * 16 + rlA) * 64
                                              + (cA ^ swA) * 16));
#pragma unroll
            for (int bg = 0; bg < 2; bg++)
                ldm_x4(b[bg], wT + (uint32_t)((wn * 32 + bg * 16 + rlW) * 64
                                              + (cW ^ swW) * 16));
#pragma unroll
            for (int mi = 0; mi < 4; mi++)
#pragma unroll
                for (int bg = 0; bg < 2; bg++) {
                    mma16(c[mi][bg * 2],     a[mi], b[bg][0], b[bg][1]);
                    mma16(c[mi][bg * 2 + 1], a[mi], b[bg][2], b[bg][3]);
                }
        }
    }

    // ---- fused epilogue: bias, elu+1, RoPE, k-sum; bf16 outputs ----
    bool isK = (jBase >= Cch);
    int bb = mBase >> 12;
    float ksum_loc[4][2];
#pragma unroll
    for (int f = 0; f < 4; f++) { ksum_loc[f][0] = 0.f; ksum_loc[f][1] = 0.f; }

#pragma unroll
    for (int mi = 0; mi < 4; mi++) {
        int mrow0 = mBase + wm * 64 + mi * 16 + g;
#pragma unroll
        for (int f = 0; f < 4; f++) {
            int j0 = jBase + wn * 32 + f * 8 + 2 * l4;
            int jm = isK ? (j0 - Cch) : j0;
            float b0 = bias[j0], b1 = bias[j0 + 1];
#pragma unroll
            for (int rr = 0; rr < 2; rr++) {
                int m = mrow0 + rr * 8;
                float re = (rr == 0 ? c[mi][f].x : c[mi][f].z) + b0;
                float im = (rr == 0 ? c[mi][f].y : c[mi][f].w) + b1;
                re = (re > 0.f) ? (re + 1.f) : __expf(re);
                im = (im > 0.f) ? (im + 1.f) : __expf(im);
                int n = m & (Ntok - 1);
                float2 cs = g_rope[(size_t)n * 192 + (jm >> 1)];
                float rre = cs.x * re - cs.y * im;
                float rim = cs.y * re + cs.x * im;
                size_t off = (size_t)m * Cch + jm;
                uint32_t pk = packbf(rre, rim);
                if (!isK) {
                    *(uint32_t*)&g_qrb[off] = pk;
                } else {
                    *(uint32_t*)&g_krb[off] = pk;
                    ksum_loc[f][0] += re;
                    ksum_loc[f][1] += im;
                }
            }
        }
    }

    if (isK) {
#pragma unroll
        for (int f = 0; f < 4; f++) {
#pragma unroll
            for (int e = 0; e < 2; e++) {
                float v = ksum_loc[f][e];
                v += __shfl_xor_sync(0xffffffffu, v, 4);
                v += __shfl_xor_sync(0xffffffffu, v, 8);
                v += __shfl_xor_sync(0xffffffffu, v, 16);
                if (g == 0) {
                    int jm = (jBase - Cch) + wn * 32 + f * 8 + 2 * l4 + e;
                    atomicAdd(&g_ksum[bb * Cch + jm], v);
                }
            }
        }
    }
}

// ---------------------------------------------------------------------------
// kv[b][h] = (1/N) k_rope^T @ v via bf16 MMA (ldmatrix.trans both operands).
// ---------------------------------------------------------------------------
#define KVTOK 512
#define KVSPL (Ntok / KVTOK)     // 8
#define KRS 80
#define KARR (KVTOK * KRS)
#define KV_SMEM (2 * KARR)
#define DPS 36

__global__ __launch_bounds__(256, 2) void kv_kernel()
{
    extern __shared__ __align__(16) uint8_t kvsm[];
    int b = blockIdx.x, h = blockIdx.y, s = blockIdx.z;
    int tid = threadIdx.x;
    int warp = tid >> 5, lane = tid & 31;
    int g = lane >> 2, l4 = lane & 3;
    int q = lane >> 3, r8 = lane & 7;

    uint32_t kB = (uint32_t)__cvta_generic_to_shared(kvsm);
    uint32_t vB = kB + KARR;

    int nBase = s * KVTOK;
    const __nv_bfloat16* kr = g_krb + ((size_t)b * Ntok + nBase) * Cch + h * DH;
    const __nv_bfloat16* vv = g_xbf + ((size_t)b * Ntok + nBase) * Cch + h * DH;

#pragma unroll
    for (int i = 0; i < 8; i++) {
        int idx = tid + i * 256;
        int row = idx >> 2, ch = idx & 3;
        uint32_t so = (uint32_t)(row * KRS + ch * 16);
        size_t go = (size_t)row * Cch + ch * 8;
        cp16(kB + so, kr + go);
        cp16(vB + so, vv + go);
    }
    asm volatile("cp.async.commit_group;");
    asm volatile("cp.async.wait_group 0;");
    __syncthreads();

    uint32_t aOffT = (uint32_t)(((q >> 1) * 8 + r8) * KRS + (q & 1) * 16);
    uint32_t bOffT = (uint32_t)(((q & 1) * 8 + r8) * KRS + (q >> 1) * 16);

    float4 c[2][4];
#pragma unroll
    for (int i = 0; i < 2; i++)
#pragma unroll
        for (int f = 0; f < 4; f++) c[i][f] = make_float4(0.f, 0.f, 0.f, 0.f);

    int tok0 = warp * 64;
#pragma unroll
    for (int ks = 0; ks < 4; ks++) {
        uint32_t tb = (uint32_t)((tok0 + ks * 16) * KRS);
        uint32_t a[2][4], bb[2][4];
#pragma unroll
        for (int mi = 0; mi < 2; mi++)
            ldm_x4t(a[mi], kB + tb + (uint32_t)(mi * 32) + aOffT);
#pragma unroll
        for (int eb = 0; eb < 2; eb++)
            ldm_x4t(bb[eb], vB + tb + (uint32_t)(eb * 32) + bOffT);
#pragma unroll
        for (int mi = 0; mi < 2; mi++)
#pragma unroll
            for (int eb = 0; eb < 2; eb++) {
                mma16(c[mi][eb * 2],     a[mi], bb[eb][0], bb[eb][1]);
                mma16(c[mi][eb * 2 + 1], a[mi], bb[eb][2], bb[eb][3]);
            }
    }

    __syncthreads();
    float* Dp = (float*)kvsm;
#pragma unroll
    for (int mi = 0; mi < 2; mi++)
#pragma unroll
        for (int f = 0; f < 4; f++) {
            int d = mi * 16 + g;
            int e = f * 8 + 2 * l4;
            float* lo = &Dp[warp * (32 * DPS) + d * DPS + e];
            float* hi = &Dp[warp * (32 * DPS) + (d + 8) * DPS + e];
            lo[0] = c[mi][f].x;  lo[1] = c[mi][f].y;
            hi[0] = c[mi][f].z;  hi[1] = c[mi][f].w;
        }
    __syncthreads();

    int d = tid >> 3, e = (tid & 7) * 4;
    float4 sum = make_float4(0.f, 0.f, 0.f, 0.f);
#pragma unroll
    for (int w = 0; w < 8; w++) {
        float4 p = *(float4*)&Dp[w * (32 * DPS) + d * DPS + e];
        sum.x += p.x; sum.y += p.y; sum.z += p.z; sum.w += p.w;
    }
    const float inv = 1.0f / (float)Ntok;
    float* dst = g_kv + (size_t)(b * NH + h) * DH * DH + d * DH + e;
    atomicAdd(dst + 0, sum.x * inv);
    atomicAdd(dst + 1, sum.y * inv);
    atomicAdd(dst + 2, sum.z * inv);
    atomicAdd(dst + 3, sum.w * inv);
}

// ---------------------------------------------------------------------------
// Finalize: tensor-core attention epilogue + chunked depthwise conv (fp32 x).
// SMEM UNION (57KB) + __launch_bounds__(384,3): 3 blocks/SM.
// ---------------------------------------------------------------------------
#define FQ_BYTES 784
#define FQ_SIZE  (32 * FQ_BYTES)            // 25088
#define FB_OFF   FQ_SIZE
#define FB_SIZE  (NH * DH * 80)             // 30720
#define FO_STRIDE 388
#define FO_SIZE  (32 * FO_STRIDE * 4)       // 49664
#define FZ_OFF   (FQ_SIZE + FB_SIZE)        // 55808
#define FIN_SMEM (FZ_OFF + NH * 32 * 4)     // 57344

__global__ __launch_bounds__(384, 3) void finalize_kernel(
    const float* __restrict__ x, const float* __restrict__ lepe_w,
    const float* __restrict__ lepe_b, float* __restrict__ out)
{
    extern __shared__ __align__(16) uint8_t fsm[];
    __nv_bfloat16* Q = (__nv_bfloat16*)fsm;
    uint8_t* Bkv = fsm + FB_OFF;
    float* O  = (float*)fsm;
    float* zs = (float*)(fsm + FZ_OFF);

    int hh = blockIdx.x, half = blockIdx.y, b = blockIdx.z;
    int t = threadIdx.x;
    int h = t >> 5, lane = t & 31;
    bool even = ((lane & 1) == 0);
    int n0 = hh * HRES + half * 32;

    uint32_t qB = (uint32_t)__cvta_generic_to_shared(Q);

    {
        const __nv_bfloat16* qsrc = g_qrb + ((size_t)b * Ntok + n0) * Cch;
#pragma unroll
        for (int i = 0; i < 4; i++) {
            int idx = i * 384 + t;
            int row = idx / 48, col = idx % 48;
            cp16(qB + (uint32_t)(row * FQ_BYTES + col * 16),
                 qsrc + (size_t)row * Cch + col * 8);
        }
        asm volatile("cp.async.commit_group;");
    }

    float km  = g_ksum[b * Cch + t] * (1.0f / (float)Ntok);
    float kmp = __shfl_xor_sync(0xffffffffu, km, 1);

    {
        const float* kvh = g_kv + (size_t)(b * NH + h) * DH * DH;
        __nv_bfloat16* Bh = (__nv_bfloat16*)(Bkv + h * (DH * 80));
#pragma unroll
        for (int d = 0; d < DH; d++) {
            float v = kvh[d * DH + lane];
            Bh[lane * 40 + d] = __float2bfloat16(v);
        }
    }

    asm volatile("cp.async.wait_group 0;");
    __syncthreads();

    {
        const float2* roperow = g_rope + (size_t)n0 * 192 + (h * 16 + (lane >> 1));
#pragma unroll
        for (int wq = 0; wq < 8; wq++) {
            float2 cs4[4];
            float  qv4[4];
#pragma unroll
            for (int i = 0; i < 4; i++) {
                int w = wq * 4 + i;
                cs4[i] = roperow[(size_t)w * 192];
                qv4[i] = __bfloat162float(Q[w * 392 + h * 32 + lane]);
            }
#pragma unroll
            for (int i = 0; i < 4; i++) {
                float rkm = even ? (cs4[i].x * km - cs4[i].y * kmp)
                                 : (cs4[i].y * kmp + cs4[i].x * km);
                float prod = qv4[i] * rkm;
#pragma unroll
                for (int o = 16; o > 0; o >>= 1)
                    prod += __shfl_xor_sync(0xffffffffu, prod, o);
                if (lane == 0) zs[h * 32 + wq * 4 + i] = 1.0f / (prod + 1e-6f);
            }
        }
    }
    __syncwarp();

    float4 c[2][4];
#pragma unroll
    for (int i = 0; i < 2; i++)
#pragma unroll
        for (int f = 0; f < 4; f++) c[i][f] = make_float4(0.f, 0.f, 0.f, 0.f);
    {
        int qq = lane >> 3, r8 = lane & 7;
        uint32_t aOff = (uint32_t)(((qq & 1) * 8 + r8) * FQ_BYTES + (qq >> 1) * 16);
        uint32_t bOff = (uint32_t)(((qq >> 1) * 8 + r8) * 80 + (qq & 1) * 16);
        uint32_t bB = (uint32_t)__cvta_generic_to_shared(Bkv) + (uint32_t)(h * DH * 80);
#pragma unroll
        for (int kk = 0; kk < 32; kk += 16) {
            uint32_t a[2][4], bb[2][4];
#pragma unroll
            for (int tf = 0; tf < 2; tf++)
                ldm_x4(a[tf], qB + (uint32_t)(tf * 16 * FQ_BYTES + (h * 32 + kk) * 2) + aOff);
#pragma unroll
            for (int bg = 0; bg < 2; bg++)
                ldm_x4(bb[bg], bB + (uint32_t)(bg * 16 * 80 + kk * 2) + bOff);
#pragma unroll
            for (int tf = 0; tf < 2; tf++)
#pragma unroll
                for (int bg = 0; bg < 2; bg++) {
                    mma16(c[tf][bg * 2],     a[tf], bb[bg][0], bb[bg][1]);
                    mma16(c[tf][bg * 2 + 1], a[tf], bb[bg][2], bb[bg][3]);
                }
        }
    }

    __syncthreads();

    {
        int g = lane >> 2, l4 = lane & 3;
#pragma unroll
        for (int tf = 0; tf < 2; tf++) {
            float zlo = zs[h * 32 + tf * 16 + g];
            float zhi = zs[h * 32 + tf * 16 + g + 8];
#pragma unroll
            for (int f = 0; f < 4; f++) {
                int e = h * 32 + f * 8 + 2 * l4;
                float* lo = &O[(tf * 16 + g) * FO_STRIDE + e];
                float* hi = &O[(tf * 16 + g + 8) * FO_STRIDE + e];
                lo[0] = c[tf][f].x * zlo;  lo[1] = c[tf][f].y * zlo;
                hi[0] = c[tf][f].z * zhi;  hi[1] = c[tf][f].w * zhi;
            }
        }
    }
    __syncthreads();

    float wl[9];
#pragma unroll
    for (int i = 0; i < 9; i++) wl[i] = lepe_w[t * 9 + i];
    float lb = lepe_b[t];

    const size_t rowStride = (size_t)HRES * Cch;
    const float* xb = x + (size_t)b * Ntok * Cch + t;
    int wb = half * 32;
    bool rok[3];
    const float* xr[3];
#pragma unroll
    for (int r = 0; r < 3; r++) {
        int yy = hh - 1 + r;
        rok[r] = (yy >= 0 && yy < HRES);
        xr[r] = xb + (size_t)(rok[r] ? yy : 0) * rowStride;
    }

    float* orow = out + ((size_t)b * Ntok + n0) * Cch + t;

#pragma unroll
    for (int ch = 0; ch < 4; ch++) {
        int base = wb + ch * 8;
        float v[3][10];
#pragma unroll
        for (int r = 0; r < 3; r++)
#pragma unroll
            for (int j = 0; j < 10; j++) {
                int col = base - 1 + j;
                bool ok = rok[r] && col >= 0 && col < HRES;
                v[r][j] = ok ? xr[r][(size_t)col * Cch] : 0.f;
            }
#pragma unroll
        for (int w = 0; w < 8; w++) {
            float lp = lb;
#pragma unroll
            for (int r = 0; r < 3; r++)
                lp += v[r][w] * wl[r * 3 + 0] + v[r][w + 1] * wl[r * 3 + 1]
                    + v[r][w + 2] * wl[r * 3 + 2];
            int wcol = ch * 8 + w;
            orow[(size_t)wcol * Cch] = lp + O[wcol * FO_STRIDE + t];
        }
    }
}

// ---------------------------------------------------------------------------
extern "C" void kernel_launch(void* const* d_in, const int* in_sizes, int n_in,
                              void* d_out, int out_size)
{
    const float* x      = (const float*)d_in[0];
    const float* qk_w   = (const float*)d_in[1];
    const float* qk_b   = (const float*)d_in[2];
    const float* lepe_w = (const float*)d_in[3];
    const float* lepe_b = (const float*)d_in[4];
    float* out = (float*)d_out;

    static bool init = false;
    if (!init) {
        cudaFuncSetAttribute(gemm_rope_tc, cudaFuncAttributeMaxDynamicSharedMemorySize, GEMM_SMEM);
        cudaFuncSetAttribute(kv_kernel, cudaFuncAttributeMaxDynamicSharedMemorySize, KV_SMEM);
        cudaFuncSetAttribute(finalize_kernel, cudaFuncAttributeMaxDynamicSharedMemorySize, FIN_SMEM);
        init = true;
    }

    setup_kernel<<<SB_W, 256>>>(x, qk_w);
    gemm_rope_tc<<<dim3(TWOC / BN, (Bsz * Ntok) / BM), 256, GEMM_SMEM>>>(qk_b);
    kv_kernel<<<dim3(Bsz, NH, KVSPL), 256, KV_SMEM>>>();
    finalize_kernel<<<dim3(HRES, 2, Bsz), 384, FIN_SMEM>>>(x, lepe_w, lepe_b, out);
}